// round 8
// baseline (speedup 1.0000x reference)
#include <cuda_runtime.h>
#include <cstdint>

#define B_SZ   2
#define SEQ    2048
#define DM     2048
#define NH     32
#define NKV    8
#define HD     64
#define NT     (B_SZ * SEQ)   // 4096 tokens

// ---------------- scratch (static device globals; no runtime allocation) ----
__device__ float g_q[(size_t)NT * DM];          // 32 MB
__device__ float g_k[(size_t)NT * NKV * HD];    //  8 MB
__device__ float g_v[(size_t)NT * NKV * HD];    //  8 MB
__device__ float g_o[(size_t)NT * DM];          // 32 MB

__device__ __forceinline__ float to_tf32(float x) {
    asm("cvt.rna.tf32.f32 %0, %1;" : "=f"(x) : "f"(x));
    return x;
}

#define MMA_TF32(c, a, b0_, b1_) \
    asm volatile("mma.sync.aligned.m16n8k8.row.col.f32.tf32.tf32.f32 " \
                 "{%0,%1,%2,%3}, {%4,%5,%6,%7}, {%8,%9}, {%0,%1,%2,%3};" \
                 : "+f"((c)[0]), "+f"((c)[1]), "+f"((c)[2]), "+f"((c)[3]) \
                 : "r"((a)[0]), "r"((a)[1]), "r"((a)[2]), "r"((a)[3]), \
                   "r"(b0_), "r"(b1_))

__device__ __forceinline__ void cp16(uint32_t dst, const void* src) {
    asm volatile("cp.async.ca.shared.global [%0], [%1], 16;" :: "r"(dst), "l"(src));
}
__device__ __forceinline__ uint32_t smem_u32(const void* p) {
    uint32_t a;
    asm("{ .reg .u64 t; cvta.to.shared.u64 t, %1; cvt.u32.u64 %0, t; }" : "=r"(a) : "l"(p));
    return a;
}

// ============ tf32 tensor GEMM: C[M,N] = A[M,K] * B[N,K]^T (row-major) ======
// 128x128 CTA tile, BK=32, 3-stage cp.async pipeline, 256 threads, occ 2.
#define BK 32
#define LDS_PAD 36
#define STAGE_F (128 * LDS_PAD)                  // floats per matrix per stage
#define STAGES 3
#define GEMM_SMEM (STAGES * 2 * STAGE_F * 4)     // 110592 B

__global__ void __launch_bounds__(256, 2)
gemm_tf32(const float* __restrict__ A, const float* __restrict__ Bm,
          float* __restrict__ C, int N, int K) {
    extern __shared__ float smem[];
    const uint32_t sb = smem_u32(smem);
    const int tid = threadIdx.x;
    const int wid = tid >> 5;
    const int lane = tid & 31;
    const int g   = lane >> 2;
    const int tig = lane & 3;
    const int wm0 = (wid & 3) * 32;
    const int wn0 = (wid >> 2) * 64;
    const int n0 = blockIdx.x * 128;
    const int m0 = blockIdx.y * 128;

    // cp.async mapping: 1024 chunks (16B) per matrix per stage, 4 per thread
    const int cr = tid >> 1;                 // base row pattern helper (unused rows below)
    (void)cr;

    float acc[2][8][4];
#pragma unroll
    for (int mt = 0; mt < 2; mt++)
#pragma unroll
        for (int nt = 0; nt < 8; nt++)
#pragma unroll
            for (int r = 0; r < 4; r++) acc[mt][nt][r] = 0.f;

    const int NITER = K / BK;

    // issue one stage's loads (A+B) for k-tile `kt` into stage slot `s`
    auto issue_stage = [&](int kt, int s) {
        const int k0 = kt * BK;
        const uint32_t abase = sb + (uint32_t)(s * 2 * STAGE_F) * 4u;
        const uint32_t bbase = abase + (uint32_t)STAGE_F * 4u;
#pragma unroll
        for (int t = 0; t < 4; t++) {
            const int e = tid + t * 256;     // 0..1023
            const int r = e >> 3;            // row 0..127
            const int c = (e & 7) * 4;       // float col 0..28
            const uint32_t soff = (uint32_t)(r * LDS_PAD + c) * 4u;
            cp16(abase + soff, A  + (size_t)(m0 + r) * K + k0 + c);
            cp16(bbase + soff, Bm + (size_t)(n0 + r) * K + k0 + c);
        }
    };

    // prologue: stages 0 .. STAGES-2
#pragma unroll
    for (int s = 0; s < STAGES - 1; s++) {
        if (s < NITER) issue_stage(s, s);
        asm volatile("cp.async.commit_group;");
    }

    for (int i = 0; i < NITER; i++) {
        asm volatile("cp.async.wait_group %0;" :: "n"(STAGES - 2));
        __syncthreads();

        const float* As = smem + (i % STAGES) * 2 * STAGE_F;
        const float* Bs = As + STAGE_F;
#pragma unroll
        for (int ks = 0; ks < 4; ks++) {
            const int k = ks * 8;
            uint32_t af[2][4], bf[8][2];
#pragma unroll
            for (int mt = 0; mt < 2; mt++) {
                const int am = wm0 + mt * 16 + g;
                af[mt][0] = __float_as_uint(to_tf32(As[(am)     * LDS_PAD + k + tig]));
                af[mt][1] = __float_as_uint(to_tf32(As[(am + 8) * LDS_PAD + k + tig]));
                af[mt][2] = __float_as_uint(to_tf32(As[(am)     * LDS_PAD + k + tig + 4]));
                af[mt][3] = __float_as_uint(to_tf32(As[(am + 8) * LDS_PAD + k + tig + 4]));
            }
#pragma unroll
            for (int nt = 0; nt < 8; nt++) {
                const int bn = wn0 + nt * 8 + g;
                bf[nt][0] = __float_as_uint(to_tf32(Bs[bn * LDS_PAD + k + tig]));
                bf[nt][1] = __float_as_uint(to_tf32(Bs[bn * LDS_PAD + k + tig + 4]));
            }
#pragma unroll
            for (int mt = 0; mt < 2; mt++)
#pragma unroll
                for (int nt = 0; nt < 8; nt++)
                    MMA_TF32(acc[mt][nt], af[mt], bf[nt][0], bf[nt][1]);
        }

        if (i + STAGES - 1 < NITER) issue_stage(i + STAGES - 1, (i + STAGES - 1) % STAGES);
        asm volatile("cp.async.commit_group;");
    }

#pragma unroll
    for (int mt = 0; mt < 2; mt++) {
        const int row = m0 + wm0 + mt * 16 + g;
#pragma unroll
        for (int nt = 0; nt < 8; nt++) {
            const int col = n0 + wn0 + nt * 8 + tig * 2;
            const float* c = acc[mt][nt];
            *reinterpret_cast<float2*>(C + (size_t)row * N + col) = make_float2(c[0], c[1]);
            *reinterpret_cast<float2*>(C + (size_t)(row + 8) * N + col) = make_float2(c[2], c[3]);
        }
    }
}

// ---------------- RoPE (in place) -------------------------------------------
__global__ void rope_kernel(float* __restrict__ buf, int nheads, int total) {
    int idx = blockIdx.x * blockDim.x + threadIdx.x;
    if (idx >= total) return;
    int d   = idx & 31;
    int h   = (idx >> 5) % nheads;
    int row = idx / (32 * nheads);
    int s   = row & (SEQ - 1);
    float inv = expf(-(float)d * (9.210340371976184f / 32.0f));
    float ang = (float)s * inv;
    float c  = cosf(ang);
    float si = sinf(ang);
    float* p = buf + (size_t)row * (nheads * HD) + h * HD;
    float x1 = p[d];
    float x2 = p[d + 32];
    p[d]      = x1 * c - x2 * si;
    p[d + 32] = x2 * c + x1 * si;
}

// ======== causal GQA flash attention via mma.sync tf32 (R7, unchanged) ======
#define APAD 68
#define ATTN_SMEM (4 * 64 * APAD * 4)

__global__ void __launch_bounds__(128)
attn_mma(const float* __restrict__ Q, const float* __restrict__ K,
         const float* __restrict__ V, float* __restrict__ O) {
    extern __shared__ float sm[];
    float* Khi = sm;
    float* Klo = sm + 64 * APAD;
    float* Vs  = sm + 2 * 64 * APAD;
    float* Ps  = sm + 3 * 64 * APAD;

    const int qb = blockIdx.x;
    const int bh = blockIdx.y;
    const int b   = bh >> 5;
    const int h   = bh & 31;
    const int kvh = h >> 2;
    const int tid = threadIdx.x;
    const int wid = tid >> 5;
    const int lane = tid & 31;
    const int g   = lane >> 2;
    const int tig = lane & 3;
    const int q0 = qb * 64;
    const int wr = wid * 16;

#pragma unroll
    for (int t = 0; t < 8; t++) {
        int e = tid + t * 128;
        int r = e >> 4;
        int c = (e & 15) * 4;
        float4 v = *reinterpret_cast<const float4*>(
            Q + (size_t)(b * SEQ + q0 + r) * DM + h * HD + c);
        *reinterpret_cast<float4*>(&Ps[r * APAD + c]) = v;
    }
    __syncthreads();
    uint32_t qhi[8][4], qlo[8][4];
#pragma unroll
    for (int ks = 0; ks < 8; ks++) {
        const int r0 = wr + g, r1 = wr + g + 8;
        const int c0 = ks * 8 + tig, c1 = c0 + 4;
        float x, hi;
        x = Ps[r0 * APAD + c0]; hi = to_tf32(x);
        qhi[ks][0] = __float_as_uint(hi); qlo[ks][0] = __float_as_uint(to_tf32(x - hi));
        x = Ps[r1 * APAD + c0]; hi = to_tf32(x);
        qhi[ks][1] = __float_as_uint(hi); qlo[ks][1] = __float_as_uint(to_tf32(x - hi));
        x = Ps[r0 * APAD + c1]; hi = to_tf32(x);
        qhi[ks][2] = __float_as_uint(hi); qlo[ks][2] = __float_as_uint(to_tf32(x - hi));
        x = Ps[r1 * APAD + c1]; hi = to_tf32(x);
        qhi[ks][3] = __float_as_uint(hi); qlo[ks][3] = __float_as_uint(to_tf32(x - hi));
    }
    __syncthreads();

    float oc[8][4];
#pragma unroll
    for (int nt = 0; nt < 8; nt++)
#pragma unroll
        for (int r = 0; r < 4; r++) oc[nt][r] = 0.f;
    float mrow0 = -1e30f, mrow1 = -1e30f, lrow0 = 0.f, lrow1 = 0.f;

    for (int kt = 0; kt <= qb; kt++) {
        __syncthreads();
#pragma unroll
        for (int t = 0; t < 8; t++) {
            int e = tid + t * 128;
            int r = e >> 4;
            int c = (e & 15) * 4;
            size_t go = (size_t)(b * SEQ + kt * 64 + r) * (NKV * HD) + kvh * HD + c;
            float4 kv = *reinterpret_cast<const float4*>(K + go);
            float4 hi, lo;
            hi.x = to_tf32(kv.x); lo.x = to_tf32(kv.x - hi.x);
            hi.y = to_tf32(kv.y); lo.y = to_tf32(kv.y - hi.y);
            hi.z = to_tf32(kv.z); lo.z = to_tf32(kv.z - hi.z);
            hi.w = to_tf32(kv.w); lo.w = to_tf32(kv.w - hi.w);
            *reinterpret_cast<float4*>(&Khi[r * APAD + c]) = hi;
            *reinterpret_cast<float4*>(&Klo[r * APAD + c]) = lo;
            float4 vv = *reinterpret_cast<const float4*>(V + go);
            vv.x = to_tf32(vv.x); vv.y = to_tf32(vv.y);
            vv.z = to_tf32(vv.z); vv.w = to_tf32(vv.w);
            *reinterpret_cast<float4*>(&Vs[r * APAD + c]) = vv;
        }
        __syncthreads();

        float sc[8][4];
#pragma unroll
        for (int nt = 0; nt < 8; nt++)
#pragma unroll
            for (int r = 0; r < 4; r++) sc[nt][r] = 0.f;
#pragma unroll
        for (int ks = 0; ks < 8; ks++) {
#pragma unroll
            for (int nt = 0; nt < 8; nt++) {
                const int key = nt * 8 + g;
                uint32_t bh0 = __float_as_uint(Khi[key * APAD + ks * 8 + tig]);
                uint32_t bh1 = __float_as_uint(Khi[key * APAD + ks * 8 + tig + 4]);
                uint32_t bl0 = __float_as_uint(Klo[key * APAD + ks * 8 + tig]);
                uint32_t bl1 = __float_as_uint(Klo[key * APAD + ks * 8 + tig + 4]);
                MMA_TF32(sc[nt], qhi[ks], bh0, bh1);
                MMA_TF32(sc[nt], qhi[ks], bl0, bl1);
                MMA_TF32(sc[nt], qlo[ks], bh0, bh1);
            }
        }

        const bool diag = (kt == qb);
        const int row0 = wr + g, row1 = row0 + 8;
        float rm0 = -1e30f, rm1 = -1e30f;
#pragma unroll
        for (int nt = 0; nt < 8; nt++) {
            const int col0 = nt * 8 + tig * 2, col1 = col0 + 1;
            float s0 = sc[nt][0] * 0.125f; if (diag && col0 > row0) s0 = -1e30f;
            float s1 = sc[nt][1] * 0.125f; if (diag && col1 > row0) s1 = -1e30f;
            float s2 = sc[nt][2] * 0.125f; if (diag && col0 > row1) s2 = -1e30f;
            float s3 = sc[nt][3] * 0.125f; if (diag && col1 > row1) s3 = -1e30f;
            sc[nt][0] = s0; sc[nt][1] = s1; sc[nt][2] = s2; sc[nt][3] = s3;
            rm0 = fmaxf(rm0, fmaxf(s0, s1));
            rm1 = fmaxf(rm1, fmaxf(s2, s3));
        }
        rm0 = fmaxf(rm0, __shfl_xor_sync(0xFFFFFFFFu, rm0, 1));
        rm0 = fmaxf(rm0, __shfl_xor_sync(0xFFFFFFFFu, rm0, 2));
        rm1 = fmaxf(rm1, __shfl_xor_sync(0xFFFFFFFFu, rm1, 1));
        rm1 = fmaxf(rm1, __shfl_xor_sync(0xFFFFFFFFu, rm1, 2));

        const float mn0 = fmaxf(mrow0, rm0), mn1 = fmaxf(mrow1, rm1);
        const float corr0 = __expf(mrow0 - mn0), corr1 = __expf(mrow1 - mn1);
        mrow0 = mn0; mrow1 = mn1;

        float rs0 = 0.f, rs1 = 0.f;
#pragma unroll
        for (int nt = 0; nt < 8; nt++) {
            float p0 = __expf(sc[nt][0] - mn0);
            float p1 = __expf(sc[nt][1] - mn0);
            float p2 = __expf(sc[nt][2] - mn1);
            float p3 = __expf(sc[nt][3] - mn1);
            rs0 += p0 + p1; rs1 += p2 + p3;
            oc[nt][0] *= corr0; oc[nt][1] *= corr0;
            oc[nt][2] *= corr1; oc[nt][3] *= corr1;
            *reinterpret_cast<float2*>(&Ps[row0 * APAD + nt * 8 + tig * 2]) =
                make_float2(to_tf32(p0), to_tf32(p1));
            *reinterpret_cast<float2*>(&Ps[row1 * APAD + nt * 8 + tig * 2]) =
                make_float2(to_tf32(p2), to_tf32(p3));
        }
        rs0 += __shfl_xor_sync(0xFFFFFFFFu, rs0, 1);
        rs0 += __shfl_xor_sync(0xFFFFFFFFu, rs0, 2);
        rs1 += __shfl_xor_sync(0xFFFFFFFFu, rs1, 1);
        rs1 += __shfl_xor_sync(0xFFFFFFFFu, rs1, 2);
        lrow0 = lrow0 * corr0 + rs0;
        lrow1 = lrow1 * corr1 + rs1;
        __syncwarp();

#pragma unroll
        for (int ks = 0; ks < 8; ks++) {
            uint32_t pa[4];
            pa[0] = __float_as_uint(Ps[row0 * APAD + ks * 8 + tig]);
            pa[1] = __float_as_uint(Ps[row1 * APAD + ks * 8 + tig]);
            pa[2] = __float_as_uint(Ps[row0 * APAD + ks * 8 + tig + 4]);
            pa[3] = __float_as_uint(Ps[row1 * APAD + ks * 8 + tig + 4]);
#pragma unroll
            for (int nt = 0; nt < 8; nt++) {
                uint32_t b0 = __float_as_uint(Vs[(ks * 8 + tig) * APAD + nt * 8 + g]);
                uint32_t b1 = __float_as_uint(Vs[(ks * 8 + tig + 4) * APAD + nt * 8 + g]);
                MMA_TF32(oc[nt], pa, b0, b1);
            }
        }
        __syncwarp();
    }

    const float inv0 = 1.0f / lrow0, inv1 = 1.0f / lrow1;
    const size_t gr0 = (size_t)(b * SEQ + q0 + wr + g);
#pragma unroll
    for (int nt = 0; nt < 8; nt++) {
        const int col = h * HD + nt * 8 + tig * 2;
        *reinterpret_cast<float2*>(O + gr0 * DM + col) =
            make_float2(oc[nt][0] * inv0, oc[nt][1] * inv0);
        *reinterpret_cast<float2*>(O + (gr0 + 8) * DM + col) =
            make_float2(oc[nt][2] * inv1, oc[nt][3] * inv1);
    }
}

// ---------------- launch ----------------------------------------------------
extern "C" void kernel_launch(void* const* d_in, const int* in_sizes, int n_in,
                              void* d_out, int out_size) {
    const float* x  = (const float*)d_in[0];
    const float* Wq = (const float*)d_in[1];
    const float* Wk = (const float*)d_in[2];
    const float* Wv = (const float*)d_in[3];
    const float* Wo = (const float*)d_in[4];
    float* out = (float*)d_out;

    float *gq, *gk, *gv, *go;
    cudaGetSymbolAddress((void**)&gq, g_q);
    cudaGetSymbolAddress((void**)&gk, g_k);
    cudaGetSymbolAddress((void**)&gv, g_v);
    cudaGetSymbolAddress((void**)&go, g_o);

    static bool attr_set = false;
    if (!attr_set) {
        cudaFuncSetAttribute(gemm_tf32, cudaFuncAttributeMaxDynamicSharedMemorySize, GEMM_SMEM);
        cudaFuncSetAttribute(attn_mma, cudaFuncAttributeMaxDynamicSharedMemorySize, ATTN_SMEM);
        attr_set = true;
    }

    // projections (tf32 mma.sync, cp.async pipelined)
    gemm_tf32<<<dim3(DM / 128, NT / 128), 256, GEMM_SMEM>>>(x, Wq, gq, DM, DM);
    gemm_tf32<<<dim3((NKV * HD) / 128, NT / 128), 256, GEMM_SMEM>>>(x, Wk, gk, NKV * HD, DM);
    gemm_tf32<<<dim3((NKV * HD) / 128, NT / 128), 256, GEMM_SMEM>>>(x, Wv, gv, NKV * HD, DM);

    // RoPE on q and k
    int tq = NT * NH * 32;
    rope_kernel<<<(tq + 255) / 256, 256>>>(gq, NH, tq);
    int tk = NT * NKV * 32;
    rope_kernel<<<(tk + 255) / 256, 256>>>(gk, NKV, tk);

    // causal GQA attention (tf32 mma flash)
    attn_mma<<<dim3(SEQ / 64, B_SZ * NH), 128, ATTN_SMEM>>>(gq, gk, gv, go);

    // output projection into d_out
    gemm_tf32<<<dim3(DM / 128, NT / 128), 256, GEMM_SMEM>>>(go, Wo, out, DM, DM);
}

// round 9
// speedup vs baseline: 1.1219x; 1.1219x over previous
#include <cuda_runtime.h>
#include <cstdint>

#define B_SZ   2
#define SEQ    2048
#define DM     2048
#define NH     32
#define NKV    8
#define HD     64
#define NT     (B_SZ * SEQ)   // 4096 tokens

// ---------------- scratch (static device globals; no runtime allocation) ----
__device__ float g_q[(size_t)NT * DM];          // 32 MB
__device__ float g_k[(size_t)NT * NKV * HD];    //  8 MB
__device__ float g_v[(size_t)NT * NKV * HD];    //  8 MB
__device__ float g_o[(size_t)NT * DM];          // 32 MB (attention writes tf32-rounded)
// tf32-rounded operand copies (rounded once, consumed by GEMMs)
__device__ float g_xt[(size_t)NT * DM];         // 32 MB
__device__ float g_wq[(size_t)DM * DM];         // 16 MB
__device__ float g_wk[(size_t)(NKV * HD) * DM]; //  4 MB
__device__ float g_wv[(size_t)(NKV * HD) * DM]; //  4 MB
__device__ float g_wo[(size_t)DM * DM];         // 16 MB

__device__ __forceinline__ float to_tf32(float x) {
    asm("cvt.rna.tf32.f32 %0, %1;" : "=f"(x) : "f"(x));
    return x;
}

#define MMA_TF32(c, a, b0_, b1_) \
    asm volatile("mma.sync.aligned.m16n8k8.row.col.f32.tf32.tf32.f32 " \
                 "{%0,%1,%2,%3}, {%4,%5,%6,%7}, {%8,%9}, {%0,%1,%2,%3};" \
                 : "+f"((c)[0]), "+f"((c)[1]), "+f"((c)[2]), "+f"((c)[3]) \
                 : "r"((a)[0]), "r"((a)[1]), "r"((a)[2]), "r"((a)[3]), \
                   "r"(b0_), "r"(b1_))

__device__ __forceinline__ void cp16(uint32_t dst, const void* src) {
    asm volatile("cp.async.ca.shared.global [%0], [%1], 16;" :: "r"(dst), "l"(src));
}
__device__ __forceinline__ uint32_t smem_u32(const void* p) {
    uint32_t a;
    asm("{ .reg .u64 t; cvta.to.shared.u64 t, %1; cvt.u32.u64 %0, t; }" : "=r"(a) : "l"(p));
    return a;
}

// ---------------- tf32 pre-rounding pass ------------------------------------
__global__ void cvt_tf32_kernel(const float4* __restrict__ src,
                                float4* __restrict__ dst, int n4) {
    int i = blockIdx.x * blockDim.x + threadIdx.x;
    if (i >= n4) return;
    float4 v = src[i];
    v.x = to_tf32(v.x); v.y = to_tf32(v.y);
    v.z = to_tf32(v.z); v.w = to_tf32(v.w);
    dst[i] = v;
}

// ============ tf32 tensor GEMM: C[M,N] = A[M,K] * B[N,K]^T (row-major) ======
// Operands must be PRE-ROUNDED to tf32 values. 128x128 CTA tile, BK=32,
// 3-stage cp.async pipeline, 256 threads, occ 2. blockIdx.z picks (B0,C0)/(B1,C1).
#define BK 32
#define LDS_PAD 36
#define STAGE_F (128 * LDS_PAD)
#define STAGES 3
#define GEMM_SMEM (STAGES * 2 * STAGE_F * 4)     // 110592 B

__global__ void __launch_bounds__(256, 2)
gemm_tf32(const float* __restrict__ A,
          const float* __restrict__ B0, float* __restrict__ C0,
          const float* __restrict__ B1, float* __restrict__ C1,
          int N, int K) {
    extern __shared__ float smem[];
    const float* Bm = blockIdx.z ? B1 : B0;
    float* C = blockIdx.z ? C1 : C0;
    const uint32_t sb = smem_u32(smem);
    const int tid = threadIdx.x;
    const int wid = tid >> 5;
    const int lane = tid & 31;
    const int g   = lane >> 2;
    const int tig = lane & 3;
    const int wm0 = (wid & 3) * 32;
    const int wn0 = (wid >> 2) * 64;
    const int n0 = blockIdx.x * 128;
    const int m0 = blockIdx.y * 128;

    float acc[2][8][4];
#pragma unroll
    for (int mt = 0; mt < 2; mt++)
#pragma unroll
        for (int nt = 0; nt < 8; nt++)
#pragma unroll
            for (int r = 0; r < 4; r++) acc[mt][nt][r] = 0.f;

    const int NITER = K / BK;

    auto issue_stage = [&](int kt, int s) {
        const int k0 = kt * BK;
        const uint32_t abase = sb + (uint32_t)(s * 2 * STAGE_F) * 4u;
        const uint32_t bbase = abase + (uint32_t)STAGE_F * 4u;
#pragma unroll
        for (int t = 0; t < 4; t++) {
            const int e = tid + t * 256;     // 0..1023
            const int r = e >> 3;            // row 0..127
            const int c = (e & 7) * 4;       // float col
            const uint32_t soff = (uint32_t)(r * LDS_PAD + c) * 4u;
            cp16(abase + soff, A  + (size_t)(m0 + r) * K + k0 + c);
            cp16(bbase + soff, Bm + (size_t)(n0 + r) * K + k0 + c);
        }
    };

#pragma unroll
    for (int s = 0; s < STAGES - 1; s++) {
        if (s < NITER) issue_stage(s, s);
        asm volatile("cp.async.commit_group;");
    }

    for (int i = 0; i < NITER; i++) {
        asm volatile("cp.async.wait_group %0;" :: "n"(STAGES - 2));
        __syncthreads();

        const float* As = smem + (i % STAGES) * 2 * STAGE_F;
        const float* Bs = As + STAGE_F;
#pragma unroll
        for (int ks = 0; ks < 4; ks++) {
            const int k = ks * 8;
            uint32_t af[2][4], bf[8][2];
#pragma unroll
            for (int mt = 0; mt < 2; mt++) {
                const int am = wm0 + mt * 16 + g;
                af[mt][0] = __float_as_uint(As[(am)     * LDS_PAD + k + tig]);
                af[mt][1] = __float_as_uint(As[(am + 8) * LDS_PAD + k + tig]);
                af[mt][2] = __float_as_uint(As[(am)     * LDS_PAD + k + tig + 4]);
                af[mt][3] = __float_as_uint(As[(am + 8) * LDS_PAD + k + tig + 4]);
            }
#pragma unroll
            for (int nt = 0; nt < 8; nt++) {
                const int bn = wn0 + nt * 8 + g;
                bf[nt][0] = __float_as_uint(Bs[bn * LDS_PAD + k + tig]);
                bf[nt][1] = __float_as_uint(Bs[bn * LDS_PAD + k + tig + 4]);
            }
#pragma unroll
            for (int mt = 0; mt < 2; mt++)
#pragma unroll
                for (int nt = 0; nt < 8; nt++)
                    MMA_TF32(acc[mt][nt], af[mt], bf[nt][0], bf[nt][1]);
        }

        if (i + STAGES - 1 < NITER) issue_stage(i + STAGES - 1, (i + STAGES - 1) % STAGES);
        asm volatile("cp.async.commit_group;");
    }

#pragma unroll
    for (int mt = 0; mt < 2; mt++) {
        const int row = m0 + wm0 + mt * 16 + g;
#pragma unroll
        for (int nt = 0; nt < 8; nt++) {
            const int col = n0 + wn0 + nt * 8 + tig * 2;
            const float* c = acc[mt][nt];
            *reinterpret_cast<float2*>(C + (size_t)row * N + col) = make_float2(c[0], c[1]);
            *reinterpret_cast<float2*>(C + (size_t)(row + 8) * N + col) = make_float2(c[2], c[3]);
        }
    }
}

// ---------------- RoPE (in place, full fp32 — feeds attention only) ---------
__global__ void rope_kernel(float* __restrict__ buf, int nheads, int total) {
    int idx = blockIdx.x * blockDim.x + threadIdx.x;
    if (idx >= total) return;
    int d   = idx & 31;
    int h   = (idx >> 5) % nheads;
    int row = idx / (32 * nheads);
    int s   = row & (SEQ - 1);
    float inv = expf(-(float)d * (9.210340371976184f / 32.0f));
    float ang = (float)s * inv;
    float c  = cosf(ang);
    float si = sinf(ang);
    float* p = buf + (size_t)row * (nheads * HD) + h * HD;
    float x1 = p[d];
    float x2 = p[d + 32];
    p[d]      = x1 * c - x2 * si;
    p[d + 32] = x2 * c + x1 * si;
}

// ======== causal GQA flash attention via mma.sync tf32 ======================
// Identical math to R7; final O store is tf32-rounded (pre-rounds the O-proj A operand).
#define APAD 68
#define ATTN_SMEM (4 * 64 * APAD * 4)

__global__ void __launch_bounds__(128)
attn_mma(const float* __restrict__ Q, const float* __restrict__ K,
         const float* __restrict__ V, float* __restrict__ O) {
    extern __shared__ float sm[];
    float* Khi = sm;
    float* Klo = sm + 64 * APAD;
    float* Vs  = sm + 2 * 64 * APAD;
    float* Ps  = sm + 3 * 64 * APAD;

    const int qb = blockIdx.x;
    const int bh = blockIdx.y;
    const int b   = bh >> 5;
    const int h   = bh & 31;
    const int kvh = h >> 2;
    const int tid = threadIdx.x;
    const int wid = tid >> 5;
    const int lane = tid & 31;
    const int g   = lane >> 2;
    const int tig = lane & 3;
    const int q0 = qb * 64;
    const int wr = wid * 16;

#pragma unroll
    for (int t = 0; t < 8; t++) {
        int e = tid + t * 128;
        int r = e >> 4;
        int c = (e & 15) * 4;
        float4 v = *reinterpret_cast<const float4*>(
            Q + (size_t)(b * SEQ + q0 + r) * DM + h * HD + c);
        *reinterpret_cast<float4*>(&Ps[r * APAD + c]) = v;
    }
    __syncthreads();
    uint32_t qhi[8][4], qlo[8][4];
#pragma unroll
    for (int ks = 0; ks < 8; ks++) {
        const int r0 = wr + g, r1 = wr + g + 8;
        const int c0 = ks * 8 + tig, c1 = c0 + 4;
        float x, hi;
        x = Ps[r0 * APAD + c0]; hi = to_tf32(x);
        qhi[ks][0] = __float_as_uint(hi); qlo[ks][0] = __float_as_uint(to_tf32(x - hi));
        x = Ps[r1 * APAD + c0]; hi = to_tf32(x);
        qhi[ks][1] = __float_as_uint(hi); qlo[ks][1] = __float_as_uint(to_tf32(x - hi));
        x = Ps[r0 * APAD + c1]; hi = to_tf32(x);
        qhi[ks][2] = __float_as_uint(hi); qlo[ks][2] = __float_as_uint(to_tf32(x - hi));
        x = Ps[r1 * APAD + c1]; hi = to_tf32(x);
        qhi[ks][3] = __float_as_uint(hi); qlo[ks][3] = __float_as_uint(to_tf32(x - hi));
    }
    __syncthreads();

    float oc[8][4];
#pragma unroll
    for (int nt = 0; nt < 8; nt++)
#pragma unroll
        for (int r = 0; r < 4; r++) oc[nt][r] = 0.f;
    float mrow0 = -1e30f, mrow1 = -1e30f, lrow0 = 0.f, lrow1 = 0.f;

    for (int kt = 0; kt <= qb; kt++) {
        __syncthreads();
#pragma unroll
        for (int t = 0; t < 8; t++) {
            int e = tid + t * 128;
            int r = e >> 4;
            int c = (e & 15) * 4;
            size_t go = (size_t)(b * SEQ + kt * 64 + r) * (NKV * HD) + kvh * HD + c;
            float4 kv = *reinterpret_cast<const float4*>(K + go);
            float4 hi, lo;
            hi.x = to_tf32(kv.x); lo.x = to_tf32(kv.x - hi.x);
            hi.y = to_tf32(kv.y); lo.y = to_tf32(kv.y - hi.y);
            hi.z = to_tf32(kv.z); lo.z = to_tf32(kv.z - hi.z);
            hi.w = to_tf32(kv.w); lo.w = to_tf32(kv.w - hi.w);
            *reinterpret_cast<float4*>(&Khi[r * APAD + c]) = hi;
            *reinterpret_cast<float4*>(&Klo[r * APAD + c]) = lo;
            float4 vv = *reinterpret_cast<const float4*>(V + go);
            vv.x = to_tf32(vv.x); vv.y = to_tf32(vv.y);
            vv.z = to_tf32(vv.z); vv.w = to_tf32(vv.w);
            *reinterpret_cast<float4*>(&Vs[r * APAD + c]) = vv;
        }
        __syncthreads();

        float sc[8][4];
#pragma unroll
        for (int nt = 0; nt < 8; nt++)
#pragma unroll
            for (int r = 0; r < 4; r++) sc[nt][r] = 0.f;
#pragma unroll
        for (int ks = 0; ks < 8; ks++) {
#pragma unroll
            for (int nt = 0; nt < 8; nt++) {
                const int key = nt * 8 + g;
                uint32_t bh0 = __float_as_uint(Khi[key * APAD + ks * 8 + tig]);
                uint32_t bh1 = __float_as_uint(Khi[key * APAD + ks * 8 + tig + 4]);
                uint32_t bl0 = __float_as_uint(Klo[key * APAD + ks * 8 + tig]);
                uint32_t bl1 = __float_as_uint(Klo[key * APAD + ks * 8 + tig + 4]);
                MMA_TF32(sc[nt], qhi[ks], bh0, bh1);
                MMA_TF32(sc[nt], qhi[ks], bl0, bl1);
                MMA_TF32(sc[nt], qlo[ks], bh0, bh1);
            }
        }

        const bool diag = (kt == qb);
        const int row0 = wr + g, row1 = row0 + 8;
        float rm0 = -1e30f, rm1 = -1e30f;
#pragma unroll
        for (int nt = 0; nt < 8; nt++) {
            const int col0 = nt * 8 + tig * 2, col1 = col0 + 1;
            float s0 = sc[nt][0] * 0.125f; if (diag && col0 > row0) s0 = -1e30f;
            float s1 = sc[nt][1] * 0.125f; if (diag && col1 > row0) s1 = -1e30f;
            float s2 = sc[nt][2] * 0.125f; if (diag && col0 > row1) s2 = -1e30f;
            float s3 = sc[nt][3] * 0.125f; if (diag && col1 > row1) s3 = -1e30f;
            sc[nt][0] = s0; sc[nt][1] = s1; sc[nt][2] = s2; sc[nt][3] = s3;
            rm0 = fmaxf(rm0, fmaxf(s0, s1));
            rm1 = fmaxf(rm1, fmaxf(s2, s3));
        }
        rm0 = fmaxf(rm0, __shfl_xor_sync(0xFFFFFFFFu, rm0, 1));
        rm0 = fmaxf(rm0, __shfl_xor_sync(0xFFFFFFFFu, rm0, 2));
        rm1 = fmaxf(rm1, __shfl_xor_sync(0xFFFFFFFFu, rm1, 1));
        rm1 = fmaxf(rm1, __shfl_xor_sync(0xFFFFFFFFu, rm1, 2));

        const float mn0 = fmaxf(mrow0, rm0), mn1 = fmaxf(mrow1, rm1);
        const float corr0 = __expf(mrow0 - mn0), corr1 = __expf(mrow1 - mn1);
        mrow0 = mn0; mrow1 = mn1;

        float rs0 = 0.f, rs1 = 0.f;
#pragma unroll
        for (int nt = 0; nt < 8; nt++) {
            float p0 = __expf(sc[nt][0] - mn0);
            float p1 = __expf(sc[nt][1] - mn0);
            float p2 = __expf(sc[nt][2] - mn1);
            float p3 = __expf(sc[nt][3] - mn1);
            rs0 += p0 + p1; rs1 += p2 + p3;
            oc[nt][0] *= corr0; oc[nt][1] *= corr0;
            oc[nt][2] *= corr1; oc[nt][3] *= corr1;
            *reinterpret_cast<float2*>(&Ps[row0 * APAD + nt * 8 + tig * 2]) =
                make_float2(to_tf32(p0), to_tf32(p1));
            *reinterpret_cast<float2*>(&Ps[row1 * APAD + nt * 8 + tig * 2]) =
                make_float2(to_tf32(p2), to_tf32(p3));
        }
        rs0 += __shfl_xor_sync(0xFFFFFFFFu, rs0, 1);
        rs0 += __shfl_xor_sync(0xFFFFFFFFu, rs0, 2);
        rs1 += __shfl_xor_sync(0xFFFFFFFFu, rs1, 1);
        rs1 += __shfl_xor_sync(0xFFFFFFFFu, rs1, 2);
        lrow0 = lrow0 * corr0 + rs0;
        lrow1 = lrow1 * corr1 + rs1;
        __syncwarp();

#pragma unroll
        for (int ks = 0; ks < 8; ks++) {
            uint32_t pa[4];
            pa[0] = __float_as_uint(Ps[row0 * APAD + ks * 8 + tig]);
            pa[1] = __float_as_uint(Ps[row1 * APAD + ks * 8 + tig]);
            pa[2] = __float_as_uint(Ps[row0 * APAD + ks * 8 + tig + 4]);
            pa[3] = __float_as_uint(Ps[row1 * APAD + ks * 8 + tig + 4]);
#pragma unroll
            for (int nt = 0; nt < 8; nt++) {
                uint32_t b0 = __float_as_uint(Vs[(ks * 8 + tig) * APAD + nt * 8 + g]);
                uint32_t b1 = __float_as_uint(Vs[(ks * 8 + tig + 4) * APAD + nt * 8 + g]);
                MMA_TF32(oc[nt], pa, b0, b1);
            }
        }
        __syncwarp();
    }

    const float inv0 = 1.0f / lrow0, inv1 = 1.0f / lrow1;
    const size_t gr0 = (size_t)(b * SEQ + q0 + wr + g);
#pragma unroll
    for (int nt = 0; nt < 8; nt++) {
        const int col = h * HD + nt * 8 + tig * 2;
        *reinterpret_cast<float2*>(O + gr0 * DM + col) =
            make_float2(to_tf32(oc[nt][0] * inv0), to_tf32(oc[nt][1] * inv0));
        *reinterpret_cast<float2*>(O + (gr0 + 8) * DM + col) =
            make_float2(to_tf32(oc[nt][2] * inv1), to_tf32(oc[nt][3] * inv1));
    }
}

// ---------------- launch ----------------------------------------------------
extern "C" void kernel_launch(void* const* d_in, const int* in_sizes, int n_in,
                              void* d_out, int out_size) {
    const float* x  = (const float*)d_in[0];
    const float* Wq = (const float*)d_in[1];
    const float* Wk = (const float*)d_in[2];
    const float* Wv = (const float*)d_in[3];
    const float* Wo = (const float*)d_in[4];
    float* out = (float*)d_out;

    float *gq, *gk, *gv, *go, *xt, *wq, *wk, *wv, *wo;
    cudaGetSymbolAddress((void**)&gq, g_q);
    cudaGetSymbolAddress((void**)&gk, g_k);
    cudaGetSymbolAddress((void**)&gv, g_v);
    cudaGetSymbolAddress((void**)&go, g_o);
    cudaGetSymbolAddress((void**)&xt, g_xt);
    cudaGetSymbolAddress((void**)&wq, g_wq);
    cudaGetSymbolAddress((void**)&wk, g_wk);
    cudaGetSymbolAddress((void**)&wv, g_wv);
    cudaGetSymbolAddress((void**)&wo, g_wo);

    static bool attr_set = false;
    if (!attr_set) {
        cudaFuncSetAttribute(gemm_tf32, cudaFuncAttributeMaxDynamicSharedMemorySize, GEMM_SMEM);
        cudaFuncSetAttribute(attn_mma, cudaFuncAttributeMaxDynamicSharedMemorySize, ATTN_SMEM);
        attr_set = true;
    }

    // pre-round operands to tf32 values
    auto cvt = [](const float* s, float* d, size_t n) {
        int n4 = (int)(n / 4);
        cvt_tf32_kernel<<<(n4 + 255) / 256, 256>>>(
            (const float4*)s, (float4*)d, n4);
    };
    cvt(x,  xt, (size_t)NT * DM);
    cvt(Wq, wq, (size_t)DM * DM);
    cvt(Wk, wk, (size_t)(NKV * HD) * DM);
    cvt(Wv, wv, (size_t)(NKV * HD) * DM);
    cvt(Wo, wo, (size_t)DM * DM);

    // Q projection
    gemm_tf32<<<dim3(DM / 128, NT / 128, 1), 256, GEMM_SMEM>>>(
        xt, wq, gq, wq, gq, DM, DM);
    // K and V projections fused in one launch (z selects)
    gemm_tf32<<<dim3((NKV * HD) / 128, NT / 128, 2), 256, GEMM_SMEM>>>(
        xt, wk, gk, wv, gv, NKV * HD, DM);

    // RoPE on q and k (full fp32)
    int tq = NT * NH * 32;
    rope_kernel<<<(tq + 255) / 256, 256>>>(gq, NH, tq);
    int tk = NT * NKV * 32;
    rope_kernel<<<(tk + 255) / 256, 256>>>(gk, NKV, tk);

    // causal GQA attention (tf32 mma flash); writes tf32-rounded O
    attn_mma<<<dim3(SEQ / 64, B_SZ * NH), 128, ATTN_SMEM>>>(gq, gk, gv, go);

    // output projection into d_out
    gemm_tf32<<<dim3(DM / 128, NT / 128, 1), 256, GEMM_SMEM>>>(
        go, wo, out, wo, out, DM, DM);
}

// round 10
// speedup vs baseline: 1.3065x; 1.1646x over previous
#include <cuda_runtime.h>
#include <cstdint>

#define B_SZ   2
#define SEQ    2048
#define DM     2048
#define NH     32
#define NKV    8
#define HD     64
#define NT     (B_SZ * SEQ)   // 4096 tokens

// ---------------- scratch (static device globals; no runtime allocation) ----
__device__ float g_q[(size_t)NT * DM];          // 32 MB
__device__ float g_k[(size_t)NT * NKV * HD];    //  8 MB
__device__ float g_v[(size_t)NT * NKV * HD];    //  8 MB
__device__ float g_o[(size_t)NT * DM];          // 32 MB (attention writes tf32-rounded)
// tf32-rounded operand copies (rounded once, consumed by GEMMs)
__device__ float g_xt[(size_t)NT * DM];         // 32 MB
__device__ float g_wq[(size_t)DM * DM];         // 16 MB
__device__ float g_wk[(size_t)(NKV * HD) * DM]; //  4 MB
__device__ float g_wv[(size_t)(NKV * HD) * DM]; //  4 MB
__device__ float g_wo[(size_t)DM * DM];         // 16 MB

__device__ __forceinline__ float to_tf32(float x) {
    asm("cvt.rna.tf32.f32 %0, %1;" : "=f"(x) : "f"(x));
    return x;
}

#define MMA_TF32(c, a, b0_, b1_) \
    asm volatile("mma.sync.aligned.m16n8k8.row.col.f32.tf32.tf32.f32 " \
                 "{%0,%1,%2,%3}, {%4,%5,%6,%7}, {%8,%9}, {%0,%1,%2,%3};" \
                 : "+f"((c)[0]), "+f"((c)[1]), "+f"((c)[2]), "+f"((c)[3]) \
                 : "r"((a)[0]), "r"((a)[1]), "r"((a)[2]), "r"((a)[3]), \
                   "r"(b0_), "r"(b1_))

__device__ __forceinline__ void cp16(uint32_t dst, const void* src) {
    asm volatile("cp.async.ca.shared.global [%0], [%1], 16;" :: "r"(dst), "l"(src));
}
__device__ __forceinline__ uint32_t smem_u32(const void* p) {
    uint32_t a;
    asm("{ .reg .u64 t; cvta.to.shared.u64 t, %1; cvt.u32.u64 %0, t; }" : "=r"(a) : "l"(p));
    return a;
}

// ---------------- tf32 pre-rounding pass ------------------------------------
__global__ void cvt_tf32_kernel(const float4* __restrict__ src,
                                float4* __restrict__ dst, int n4) {
    int i = blockIdx.x * blockDim.x + threadIdx.x;
    if (i >= n4) return;
    float4 v = src[i];
    v.x = to_tf32(v.x); v.y = to_tf32(v.y);
    v.z = to_tf32(v.z); v.w = to_tf32(v.w);
    dst[i] = v;
}

// ============ tf32 tensor GEMM: C[M,N] = A[M,K] * B[N,K]^T (row-major) ======
// Operands must be PRE-ROUNDED to tf32 values. 128x128 CTA tile, BK=32,
// 3-stage cp.async pipeline, 256 threads, occ 2. blockIdx.z picks (B0,C0)/(B1,C1).
#define BK 32
#define LDS_PAD 36
#define STAGE_F (128 * LDS_PAD)
#define STAGES 3
#define GEMM_SMEM (STAGES * 2 * STAGE_F * 4)     // 110592 B

__global__ void __launch_bounds__(256, 2)
gemm_tf32(const float* __restrict__ A,
          const float* __restrict__ B0, float* __restrict__ C0,
          const float* __restrict__ B1, float* __restrict__ C1,
          int N, int K) {
    extern __shared__ float smem[];
    const float* Bm = blockIdx.z ? B1 : B0;
    float* C = blockIdx.z ? C1 : C0;
    const uint32_t sb = smem_u32(smem);
    const int tid = threadIdx.x;
    const int wid = tid >> 5;
    const int lane = tid & 31;
    const int g   = lane >> 2;
    const int tig = lane & 3;
    const int wm0 = (wid & 3) * 32;
    const int wn0 = (wid >> 2) * 64;
    const int n0 = blockIdx.x * 128;
    const int m0 = blockIdx.y * 128;

    float acc[2][8][4];
#pragma unroll
    for (int mt = 0; mt < 2; mt++)
#pragma unroll
        for (int nt = 0; nt < 8; nt++)
#pragma unroll
            for (int r = 0; r < 4; r++) acc[mt][nt][r] = 0.f;

    const int NITER = K / BK;

    auto issue_stage = [&](int kt, int s) {
        const int k0 = kt * BK;
        const uint32_t abase = sb + (uint32_t)(s * 2 * STAGE_F) * 4u;
        const uint32_t bbase = abase + (uint32_t)STAGE_F * 4u;
#pragma unroll
        for (int t = 0; t < 4; t++) {
            const int e = tid + t * 256;     // 0..1023
            const int r = e >> 3;            // row 0..127
            const int c = (e & 7) * 4;       // float col
            const uint32_t soff = (uint32_t)(r * LDS_PAD + c) * 4u;
            cp16(abase + soff, A  + (size_t)(m0 + r) * K + k0 + c);
            cp16(bbase + soff, Bm + (size_t)(n0 + r) * K + k0 + c);
        }
    };

#pragma unroll
    for (int s = 0; s < STAGES - 1; s++) {
        if (s < NITER) issue_stage(s, s);
        asm volatile("cp.async.commit_group;");
    }

    for (int i = 0; i < NITER; i++) {
        asm volatile("cp.async.wait_group %0;" :: "n"(STAGES - 2));
        __syncthreads();

        const float* As = smem + (i % STAGES) * 2 * STAGE_F;
        const float* Bs = As + STAGE_F;
#pragma unroll
        for (int ks = 0; ks < 4; ks++) {
            const int k = ks * 8;
            uint32_t af[2][4], bf[8][2];
#pragma unroll
            for (int mt = 0; mt < 2; mt++) {
                const int am = wm0 + mt * 16 + g;
                af[mt][0] = __float_as_uint(As[(am)     * LDS_PAD + k + tig]);
                af[mt][1] = __float_as_uint(As[(am + 8) * LDS_PAD + k + tig]);
                af[mt][2] = __float_as_uint(As[(am)     * LDS_PAD + k + tig + 4]);
                af[mt][3] = __float_as_uint(As[(am + 8) * LDS_PAD + k + tig + 4]);
            }
#pragma unroll
            for (int nt = 0; nt < 8; nt++) {
                const int bn = wn0 + nt * 8 + g;
                bf[nt][0] = __float_as_uint(Bs[bn * LDS_PAD + k + tig]);
                bf[nt][1] = __float_as_uint(Bs[bn * LDS_PAD + k + tig + 4]);
            }
#pragma unroll
            for (int mt = 0; mt < 2; mt++)
#pragma unroll
                for (int nt = 0; nt < 8; nt++)
                    MMA_TF32(acc[mt][nt], af[mt], bf[nt][0], bf[nt][1]);
        }

        if (i + STAGES - 1 < NITER) issue_stage(i + STAGES - 1, (i + STAGES - 1) % STAGES);
        asm volatile("cp.async.commit_group;");
    }

#pragma unroll
    for (int mt = 0; mt < 2; mt++) {
        const int row = m0 + wm0 + mt * 16 + g;
#pragma unroll
        for (int nt = 0; nt < 8; nt++) {
            const int col = n0 + wn0 + nt * 8 + tig * 2;
            const float* c = acc[mt][nt];
            *reinterpret_cast<float2*>(C + (size_t)row * N + col) = make_float2(c[0], c[1]);
            *reinterpret_cast<float2*>(C + (size_t)(row + 8) * N + col) = make_float2(c[2], c[3]);
        }
    }
}

// ---------------- RoPE (in place, full fp32 — feeds attention only) ---------
__global__ void rope_kernel(float* __restrict__ buf, int nheads, int total) {
    int idx = blockIdx.x * blockDim.x + threadIdx.x;
    if (idx >= total) return;
    int d   = idx & 31;
    int h   = (idx >> 5) % nheads;
    int row = idx / (32 * nheads);
    int s   = row & (SEQ - 1);
    float inv = expf(-(float)d * (9.210340371976184f / 32.0f));
    float ang = (float)s * inv;
    float c  = cosf(ang);
    float si = sinf(ang);
    float* p = buf + (size_t)row * (nheads * HD) + h * HD;
    float x1 = p[d];
    float x2 = p[d + 32];
    p[d]      = x1 * c - x2 * si;
    p[d + 32] = x2 * c + x1 * si;
}

// ======== causal GQA flash attention via mma.sync tf32 (plain QK) ===========
// Block: 128 threads (4 warps), 64 q-rows for one (b,h). Key tiles of 64.
// QK and PV both single-pass tf32-rna. Smem: Ks, Vs, Ps -> occ 4.
#define APAD 68
#define ATTN_SMEM (3 * 64 * APAD * 4)   // 52224 B

__global__ void __launch_bounds__(128)
attn_mma(const float* __restrict__ Q, const float* __restrict__ K,
         const float* __restrict__ V, float* __restrict__ O) {
    extern __shared__ float sm[];
    float* Ks = sm;
    float* Vs = sm + 64 * APAD;
    float* Ps = sm + 2 * 64 * APAD;

    const int qb = blockIdx.x;
    const int bh = blockIdx.y;
    const int b   = bh >> 5;
    const int h   = bh & 31;
    const int kvh = h >> 2;
    const int tid = threadIdx.x;
    const int wid = tid >> 5;
    const int lane = tid & 31;
    const int g   = lane >> 2;
    const int tig = lane & 3;
    const int q0 = qb * 64;
    const int wr = wid * 16;

    // ---- stage Q tile (64 rows x 16 float4) into Ps, pull plain a-frags ----
#pragma unroll
    for (int t = 0; t < 8; t++) {
        int e = tid + t * 128;
        int r = e >> 4;
        int c = (e & 15) * 4;
        float4 v = *reinterpret_cast<const float4*>(
            Q + (size_t)(b * SEQ + q0 + r) * DM + h * HD + c);
        *reinterpret_cast<float4*>(&Ps[r * APAD + c]) = v;
    }
    __syncthreads();
    uint32_t qa[8][4];
#pragma unroll
    for (int ks = 0; ks < 8; ks++) {
        const int r0 = wr + g, r1 = wr + g + 8;
        const int c0 = ks * 8 + tig, c1 = c0 + 4;
        qa[ks][0] = __float_as_uint(to_tf32(Ps[r0 * APAD + c0]));
        qa[ks][1] = __float_as_uint(to_tf32(Ps[r1 * APAD + c0]));
        qa[ks][2] = __float_as_uint(to_tf32(Ps[r0 * APAD + c1]));
        qa[ks][3] = __float_as_uint(to_tf32(Ps[r1 * APAD + c1]));
    }
    __syncthreads();

    float oc[8][4];
#pragma unroll
    for (int nt = 0; nt < 8; nt++)
#pragma unroll
        for (int r = 0; r < 4; r++) oc[nt][r] = 0.f;
    float mrow0 = -1e30f, mrow1 = -1e30f, lrow0 = 0.f, lrow1 = 0.f;

    for (int kt = 0; kt <= qb; kt++) {
        __syncthreads();   // prior PV reads of Vs done before overwrite
        // ---- load K and V tiles (rna-rounded): 64 rows x 16 float4 ----
#pragma unroll
        for (int t = 0; t < 8; t++) {
            int e = tid + t * 128;
            int r = e >> 4;
            int c = (e & 15) * 4;
            size_t go = (size_t)(b * SEQ + kt * 64 + r) * (NKV * HD) + kvh * HD + c;
            float4 kv = *reinterpret_cast<const float4*>(K + go);
            kv.x = to_tf32(kv.x); kv.y = to_tf32(kv.y);
            kv.z = to_tf32(kv.z); kv.w = to_tf32(kv.w);
            *reinterpret_cast<float4*>(&Ks[r * APAD + c]) = kv;
            float4 vv = *reinterpret_cast<const float4*>(V + go);
            vv.x = to_tf32(vv.x); vv.y = to_tf32(vv.y);
            vv.z = to_tf32(vv.z); vv.w = to_tf32(vv.w);
            *reinterpret_cast<float4*>(&Vs[r * APAD + c]) = vv;
        }
        __syncthreads();

        // ---- S = Q K^T (plain tf32) ----
        float sc[8][4];
#pragma unroll
        for (int nt = 0; nt < 8; nt++)
#pragma unroll
            for (int r = 0; r < 4; r++) sc[nt][r] = 0.f;
#pragma unroll
        for (int ks = 0; ks < 8; ks++) {
#pragma unroll
            for (int nt = 0; nt < 8; nt++) {
                const int key = nt * 8 + g;
                uint32_t b0 = __float_as_uint(Ks[key * APAD + ks * 8 + tig]);
                uint32_t b1 = __float_as_uint(Ks[key * APAD + ks * 8 + tig + 4]);
                MMA_TF32(sc[nt], qa[ks], b0, b1);
            }
        }

        // ---- scale + causal mask + row max ----
        const bool diag = (kt == qb);
        const int row0 = wr + g, row1 = row0 + 8;
        float rm0 = -1e30f, rm1 = -1e30f;
#pragma unroll
        for (int nt = 0; nt < 8; nt++) {
            const int col0 = nt * 8 + tig * 2, col1 = col0 + 1;
            float s0 = sc[nt][0] * 0.125f; if (diag && col0 > row0) s0 = -1e30f;
            float s1 = sc[nt][1] * 0.125f; if (diag && col1 > row0) s1 = -1e30f;
            float s2 = sc[nt][2] * 0.125f; if (diag && col0 > row1) s2 = -1e30f;
            float s3 = sc[nt][3] * 0.125f; if (diag && col1 > row1) s3 = -1e30f;
            sc[nt][0] = s0; sc[nt][1] = s1; sc[nt][2] = s2; sc[nt][3] = s3;
            rm0 = fmaxf(rm0, fmaxf(s0, s1));
            rm1 = fmaxf(rm1, fmaxf(s2, s3));
        }
        rm0 = fmaxf(rm0, __shfl_xor_sync(0xFFFFFFFFu, rm0, 1));
        rm0 = fmaxf(rm0, __shfl_xor_sync(0xFFFFFFFFu, rm0, 2));
        rm1 = fmaxf(rm1, __shfl_xor_sync(0xFFFFFFFFu, rm1, 1));
        rm1 = fmaxf(rm1, __shfl_xor_sync(0xFFFFFFFFu, rm1, 2));

        const float mn0 = fmaxf(mrow0, rm0), mn1 = fmaxf(mrow1, rm1);
        const float corr0 = __expf(mrow0 - mn0), corr1 = __expf(mrow1 - mn1);
        mrow0 = mn0; mrow1 = mn1;

        // ---- P = exp(S - m), rescale O, stash P (warp-private rows) ----
        float rs0 = 0.f, rs1 = 0.f;
#pragma unroll
        for (int nt = 0; nt < 8; nt++) {
            float p0 = __expf(sc[nt][0] - mn0);
            float p1 = __expf(sc[nt][1] - mn0);
            float p2 = __expf(sc[nt][2] - mn1);
            float p3 = __expf(sc[nt][3] - mn1);
            rs0 += p0 + p1; rs1 += p2 + p3;
            oc[nt][0] *= corr0; oc[nt][1] *= corr0;
            oc[nt][2] *= corr1; oc[nt][3] *= corr1;
            *reinterpret_cast<float2*>(&Ps[row0 * APAD + nt * 8 + tig * 2]) =
                make_float2(to_tf32(p0), to_tf32(p1));
            *reinterpret_cast<float2*>(&Ps[row1 * APAD + nt * 8 + tig * 2]) =
                make_float2(to_tf32(p2), to_tf32(p3));
        }
        rs0 += __shfl_xor_sync(0xFFFFFFFFu, rs0, 1);
        rs0 += __shfl_xor_sync(0xFFFFFFFFu, rs0, 2);
        rs1 += __shfl_xor_sync(0xFFFFFFFFu, rs1, 1);
        rs1 += __shfl_xor_sync(0xFFFFFFFFu, rs1, 2);
        lrow0 = lrow0 * corr0 + rs0;
        lrow1 = lrow1 * corr1 + rs1;
        __syncwarp();

        // ---- O += P V ----
#pragma unroll
        for (int ks = 0; ks < 8; ks++) {
            uint32_t pa[4];
            pa[0] = __float_as_uint(Ps[row0 * APAD + ks * 8 + tig]);
            pa[1] = __float_as_uint(Ps[row1 * APAD + ks * 8 + tig]);
            pa[2] = __float_as_uint(Ps[row0 * APAD + ks * 8 + tig + 4]);
            pa[3] = __float_as_uint(Ps[row1 * APAD + ks * 8 + tig + 4]);
#pragma unroll
            for (int nt = 0; nt < 8; nt++) {
                uint32_t b0 = __float_as_uint(Vs[(ks * 8 + tig) * APAD + nt * 8 + g]);
                uint32_t b1 = __float_as_uint(Vs[(ks * 8 + tig + 4) * APAD + nt * 8 + g]);
                MMA_TF32(oc[nt], pa, b0, b1);
            }
        }
        __syncwarp();   // Ps reads done before next tile's stores
    }

    // ---- finalize (tf32-rounded store pre-rounds the O-proj A operand) ----
    const float inv0 = 1.0f / lrow0, inv1 = 1.0f / lrow1;
    const size_t gr0 = (size_t)(b * SEQ + q0 + wr + g);
#pragma unroll
    for (int nt = 0; nt < 8; nt++) {
        const int col = h * HD + nt * 8 + tig * 2;
        *reinterpret_cast<float2*>(O + gr0 * DM + col) =
            make_float2(to_tf32(oc[nt][0] * inv0), to_tf32(oc[nt][1] * inv0));
        *reinterpret_cast<float2*>(O + (gr0 + 8) * DM + col) =
            make_float2(to_tf32(oc[nt][2] * inv1), to_tf32(oc[nt][3] * inv1));
    }
}

// ---------------- launch ----------------------------------------------------
extern "C" void kernel_launch(void* const* d_in, const int* in_sizes, int n_in,
                              void* d_out, int out_size) {
    const float* x  = (const float*)d_in[0];
    const float* Wq = (const float*)d_in[1];
    const float* Wk = (const float*)d_in[2];
    const float* Wv = (const float*)d_in[3];
    const float* Wo = (const float*)d_in[4];
    float* out = (float*)d_out;

    float *gq, *gk, *gv, *go, *xt, *wq, *wk, *wv, *wo;
    cudaGetSymbolAddress((void**)&gq, g_q);
    cudaGetSymbolAddress((void**)&gk, g_k);
    cudaGetSymbolAddress((void**)&gv, g_v);
    cudaGetSymbolAddress((void**)&go, g_o);
    cudaGetSymbolAddress((void**)&xt, g_xt);
    cudaGetSymbolAddress((void**)&wq, g_wq);
    cudaGetSymbolAddress((void**)&wk, g_wk);
    cudaGetSymbolAddress((void**)&wv, g_wv);
    cudaGetSymbolAddress((void**)&wo, g_wo);

    static bool attr_set = false;
    if (!attr_set) {
        cudaFuncSetAttribute(gemm_tf32, cudaFuncAttributeMaxDynamicSharedMemorySize, GEMM_SMEM);
        cudaFuncSetAttribute(attn_mma, cudaFuncAttributeMaxDynamicSharedMemorySize, ATTN_SMEM);
        attr_set = true;
    }

    // pre-round operands to tf32 values
    auto cvt = [](const float* s, float* d, size_t n) {
        int n4 = (int)(n / 4);
        cvt_tf32_kernel<<<(n4 + 255) / 256, 256>>>(
            (const float4*)s, (float4*)d, n4);
    };
    cvt(x,  xt, (size_t)NT * DM);
    cvt(Wq, wq, (size_t)DM * DM);
    cvt(Wk, wk, (size_t)(NKV * HD) * DM);
    cvt(Wv, wv, (size_t)(NKV * HD) * DM);
    cvt(Wo, wo, (size_t)DM * DM);

    // Q projection
    gemm_tf32<<<dim3(DM / 128, NT / 128, 1), 256, GEMM_SMEM>>>(
        xt, wq, gq, wq, gq, DM, DM);
    // K and V projections fused in one launch (z selects)
    gemm_tf32<<<dim3((NKV * HD) / 128, NT / 128, 2), 256, GEMM_SMEM>>>(
        xt, wk, gk, wv, gv, NKV * HD, DM);

    // RoPE on q and k (full fp32)
    int tq = NT * NH * 32;
    rope_kernel<<<(tq + 255) / 256, 256>>>(gq, NH, tq);
    int tk = NT * NKV * 32;
    rope_kernel<<<(tk + 255) / 256, 256>>>(gk, NKV, tk);

    // causal GQA attention (tf32 mma flash, plain QK)
    attn_mma<<<dim3(SEQ / 64, B_SZ * NH), 128, ATTN_SMEM>>>(gq, gk, gv, go);

    // output projection into d_out
    gemm_tf32<<<dim3(DM / 128, NT / 128, 1), 256, GEMM_SMEM>>>(
        go, wo, out, wo, out, DM, DM);
}

// round 11
// speedup vs baseline: 1.3504x; 1.0336x over previous
#include <cuda_runtime.h>
#include <cstdint>

#define B_SZ   2
#define SEQ    2048
#define DM     2048
#define NH     32
#define NKV    8
#define HD     64
#define NT     (B_SZ * SEQ)   // 4096 tokens

// ---------------- scratch (static device globals; no runtime allocation) ----
__device__ float g_q[(size_t)NT * DM];          // 32 MB
__device__ float g_k[(size_t)NT * NKV * HD];    //  8 MB
__device__ float g_v[(size_t)NT * NKV * HD];    //  8 MB
__device__ float g_o[(size_t)NT * DM];          // 32 MB (attention writes tf32-rounded)
__device__ float g_xt[(size_t)NT * DM];         // 32 MB
__device__ float g_wq[(size_t)DM * DM];         // 16 MB
__device__ float g_wk[(size_t)(NKV * HD) * DM]; //  4 MB
__device__ float g_wv[(size_t)(NKV * HD) * DM]; //  4 MB
__device__ float g_wo[(size_t)DM * DM];         // 16 MB

__device__ __forceinline__ float to_tf32(float x) {
    asm("cvt.rna.tf32.f32 %0, %1;" : "=f"(x) : "f"(x));
    return x;
}

#define MMA_TF32(c, a, b0_, b1_) \
    asm volatile("mma.sync.aligned.m16n8k8.row.col.f32.tf32.tf32.f32 " \
                 "{%0,%1,%2,%3}, {%4,%5,%6,%7}, {%8,%9}, {%0,%1,%2,%3};" \
                 : "+f"((c)[0]), "+f"((c)[1]), "+f"((c)[2]), "+f"((c)[3]) \
                 : "r"((a)[0]), "r"((a)[1]), "r"((a)[2]), "r"((a)[3]), \
                   "r"(b0_), "r"(b1_))

__device__ __forceinline__ void cp16(uint32_t dst, const void* src) {
    asm volatile("cp.async.ca.shared.global [%0], [%1], 16;" :: "r"(dst), "l"(src));
}
__device__ __forceinline__ uint32_t smem_u32(const void* p) {
    uint32_t a;
    asm("{ .reg .u64 t; cvta.to.shared.u64 t, %1; cvt.u32.u64 %0, t; }" : "=r"(a) : "l"(p));
    return a;
}

// ---------------- tf32 pre-rounding pass (all 5 tensors, one launch) --------
__global__ void cvt_all_kernel(const float4* __restrict__ s0, float4* __restrict__ d0, int n0,
                               const float4* __restrict__ s1, float4* __restrict__ d1, int n1,
                               const float4* __restrict__ s2, float4* __restrict__ d2, int n2,
                               const float4* __restrict__ s3, float4* __restrict__ d3, int n3,
                               const float4* __restrict__ s4, float4* __restrict__ d4, int n4) {
    const int stride = gridDim.x * blockDim.x;
    const int gid = blockIdx.x * blockDim.x + threadIdx.x;
#define CVT_SEG(S, D, N) \
    for (int i = gid; i < (N); i += stride) { \
        float4 v = (S)[i]; \
        v.x = to_tf32(v.x); v.y = to_tf32(v.y); \
        v.z = to_tf32(v.z); v.w = to_tf32(v.w); \
        (D)[i] = v; \
    }
    CVT_SEG(s0, d0, n0)
    CVT_SEG(s1, d1, n1)
    CVT_SEG(s2, d2, n2)
    CVT_SEG(s3, d3, n3)
    CVT_SEG(s4, d4, n4)
#undef CVT_SEG
}

// ============ tf32 tensor GEMM core (pre-rounded operands) ==================
#define BK 32
#define LDS_PAD 36
#define STAGE_F (128 * LDS_PAD)
#define STAGES 3
#define GEMM_SMEM (STAGES * 2 * STAGE_F * 4)     // 110592 B

__device__ __forceinline__ void gemm_tile(const float* __restrict__ A,
                                          const float* __restrict__ Bm,
                                          float* __restrict__ C,
                                          int N, int K, int m0, int n0,
                                          float* smem) {
    const uint32_t sb = smem_u32(smem);
    const int tid = threadIdx.x;
    const int wid = tid >> 5;
    const int lane = tid & 31;
    const int g   = lane >> 2;
    const int tig = lane & 3;
    const int wm0 = (wid & 3) * 32;
    const int wn0 = (wid >> 2) * 64;

    float acc[2][8][4];
#pragma unroll
    for (int mt = 0; mt < 2; mt++)
#pragma unroll
        for (int nt = 0; nt < 8; nt++)
#pragma unroll
            for (int r = 0; r < 4; r++) acc[mt][nt][r] = 0.f;

    const int NITER = K / BK;

    auto issue_stage = [&](int kt, int s) {
        const int k0 = kt * BK;
        const uint32_t abase = sb + (uint32_t)(s * 2 * STAGE_F) * 4u;
        const uint32_t bbase = abase + (uint32_t)STAGE_F * 4u;
#pragma unroll
        for (int t = 0; t < 4; t++) {
            const int e = tid + t * 256;
            const int r = e >> 3;
            const int c = (e & 7) * 4;
            const uint32_t soff = (uint32_t)(r * LDS_PAD + c) * 4u;
            cp16(abase + soff, A  + (size_t)(m0 + r) * K + k0 + c);
            cp16(bbase + soff, Bm + (size_t)(n0 + r) * K + k0 + c);
        }
    };

#pragma unroll
    for (int s = 0; s < STAGES - 1; s++) {
        if (s < NITER) issue_stage(s, s);
        asm volatile("cp.async.commit_group;");
    }

    for (int i = 0; i < NITER; i++) {
        asm volatile("cp.async.wait_group %0;" :: "n"(STAGES - 2));
        __syncthreads();

        const float* As = smem + (i % STAGES) * 2 * STAGE_F;
        const float* Bs = As + STAGE_F;
#pragma unroll
        for (int ks = 0; ks < 4; ks++) {
            const int k = ks * 8;
            uint32_t af[2][4], bf[8][2];
#pragma unroll
            for (int mt = 0; mt < 2; mt++) {
                const int am = wm0 + mt * 16 + g;
                af[mt][0] = __float_as_uint(As[(am)     * LDS_PAD + k + tig]);
                af[mt][1] = __float_as_uint(As[(am + 8) * LDS_PAD + k + tig]);
                af[mt][2] = __float_as_uint(As[(am)     * LDS_PAD + k + tig + 4]);
                af[mt][3] = __float_as_uint(As[(am + 8) * LDS_PAD + k + tig + 4]);
            }
#pragma unroll
            for (int nt = 0; nt < 8; nt++) {
                const int bn = wn0 + nt * 8 + g;
                bf[nt][0] = __float_as_uint(Bs[bn * LDS_PAD + k + tig]);
                bf[nt][1] = __float_as_uint(Bs[bn * LDS_PAD + k + tig + 4]);
            }
#pragma unroll
            for (int mt = 0; mt < 2; mt++)
#pragma unroll
                for (int nt = 0; nt < 8; nt++)
                    MMA_TF32(acc[mt][nt], af[mt], bf[nt][0], bf[nt][1]);
        }

        if (i + STAGES - 1 < NITER) issue_stage(i + STAGES - 1, (i + STAGES - 1) % STAGES);
        asm volatile("cp.async.commit_group;");
    }

#pragma unroll
    for (int mt = 0; mt < 2; mt++) {
        const int row = m0 + wm0 + mt * 16 + g;
#pragma unroll
        for (int nt = 0; nt < 8; nt++) {
            const int col = n0 + wn0 + nt * 8 + tig * 2;
            const float* c = acc[mt][nt];
            *reinterpret_cast<float2*>(C + (size_t)row * N + col) = make_float2(c[0], c[1]);
            *reinterpret_cast<float2*>(C + (size_t)(row + 8) * N + col) = make_float2(c[2], c[3]);
        }
    }
}

// Q + K + V projections in one launch. bid 0..511 -> Q, 512..639 -> K, 640..767 -> V.
__global__ void __launch_bounds__(256, 2)
gemm_qkv(const float* __restrict__ A,
         const float* __restrict__ Bq, float* __restrict__ Cq,
         const float* __restrict__ Bk, float* __restrict__ Ck,
         const float* __restrict__ Bv, float* __restrict__ Cv) {
    extern __shared__ float smem[];
    const int bid = blockIdx.x;
    if (bid < 512) {
        gemm_tile(A, Bq, Cq, DM, DM, (bid >> 4) * 128, (bid & 15) * 128, smem);
    } else if (bid < 640) {
        const int t = bid - 512;
        gemm_tile(A, Bk, Ck, NKV * HD, DM, (t >> 2) * 128, (t & 3) * 128, smem);
    } else {
        const int t = bid - 640;
        gemm_tile(A, Bv, Cv, NKV * HD, DM, (t >> 2) * 128, (t & 3) * 128, smem);
    }
}

// O projection (single matrix)
__global__ void __launch_bounds__(256, 2)
gemm_single(const float* __restrict__ A, const float* __restrict__ Bm,
            float* __restrict__ C, int N, int K) {
    extern __shared__ float smem[];
    gemm_tile(A, Bm, C, N, K, blockIdx.y * 128, blockIdx.x * 128, smem);
}

// ---------------- RoPE (q and k in one launch) ------------------------------
__global__ void rope_all(float* __restrict__ q, float* __restrict__ k,
                         int tq, int total) {
    int idx = blockIdx.x * blockDim.x + threadIdx.x;
    if (idx >= total) return;
    float* buf;
    int nheads;
    if (idx < tq) { buf = q; nheads = NH; }
    else          { idx -= tq; buf = k; nheads = NKV; }
    int d   = idx & 31;
    int h   = (idx >> 5) % nheads;
    int row = idx / (32 * nheads);
    int s   = row & (SEQ - 1);
    float inv = expf(-(float)d * (9.210340371976184f / 32.0f));
    float ang = (float)s * inv;
    float c  = cosf(ang);
    float si = sinf(ang);
    float* p = buf + (size_t)row * (nheads * HD) + h * HD;
    float x1 = p[d];
    float x2 = p[d + 32];
    p[d]      = x1 * c - x2 * si;
    p[d + 32] = x2 * c + x1 * si;
}

// ======== causal GQA flash attention via mma.sync tf32 (plain QK) ===========
#define APAD 68
#define ATTN_SMEM (3 * 64 * APAD * 4)   // 52224 B

__global__ void __launch_bounds__(128)
attn_mma(const float* __restrict__ Q, const float* __restrict__ K,
         const float* __restrict__ V, float* __restrict__ O) {
    extern __shared__ float sm[];
    float* Ks = sm;
    float* Vs = sm + 64 * APAD;
    float* Ps = sm + 2 * 64 * APAD;

    // longest-first: high-qb (most key tiles) blocks launch first
    const int qb = (int)gridDim.x - 1 - (int)blockIdx.x;
    const int bh = blockIdx.y;
    const int b   = bh >> 5;
    const int h   = bh & 31;
    const int kvh = h >> 2;
    const int tid = threadIdx.x;
    const int wid = tid >> 5;
    const int lane = tid & 31;
    const int g   = lane >> 2;
    const int tig = lane & 3;
    const int q0 = qb * 64;
    const int wr = wid * 16;

#pragma unroll
    for (int t = 0; t < 8; t++) {
        int e = tid + t * 128;
        int r = e >> 4;
        int c = (e & 15) * 4;
        float4 v = *reinterpret_cast<const float4*>(
            Q + (size_t)(b * SEQ + q0 + r) * DM + h * HD + c);
        *reinterpret_cast<float4*>(&Ps[r * APAD + c]) = v;
    }
    __syncthreads();
    uint32_t qa[8][4];
#pragma unroll
    for (int ks = 0; ks < 8; ks++) {
        const int r0 = wr + g, r1 = wr + g + 8;
        const int c0 = ks * 8 + tig, c1 = c0 + 4;
        qa[ks][0] = __float_as_uint(to_tf32(Ps[r0 * APAD + c0]));
        qa[ks][1] = __float_as_uint(to_tf32(Ps[r1 * APAD + c0]));
        qa[ks][2] = __float_as_uint(to_tf32(Ps[r0 * APAD + c1]));
        qa[ks][3] = __float_as_uint(to_tf32(Ps[r1 * APAD + c1]));
    }
    __syncthreads();

    float oc[8][4];
#pragma unroll
    for (int nt = 0; nt < 8; nt++)
#pragma unroll
        for (int r = 0; r < 4; r++) oc[nt][r] = 0.f;
    float mrow0 = -1e30f, mrow1 = -1e30f, lrow0 = 0.f, lrow1 = 0.f;

    for (int kt = 0; kt <= qb; kt++) {
        __syncthreads();
#pragma unroll
        for (int t = 0; t < 8; t++) {
            int e = tid + t * 128;
            int r = e >> 4;
            int c = (e & 15) * 4;
            size_t go = (size_t)(b * SEQ + kt * 64 + r) * (NKV * HD) + kvh * HD + c;
            float4 kv = *reinterpret_cast<const float4*>(K + go);
            kv.x = to_tf32(kv.x); kv.y = to_tf32(kv.y);
            kv.z = to_tf32(kv.z); kv.w = to_tf32(kv.w);
            *reinterpret_cast<float4*>(&Ks[r * APAD + c]) = kv;
            float4 vv = *reinterpret_cast<const float4*>(V + go);
            vv.x = to_tf32(vv.x); vv.y = to_tf32(vv.y);
            vv.z = to_tf32(vv.z); vv.w = to_tf32(vv.w);
            *reinterpret_cast<float4*>(&Vs[r * APAD + c]) = vv;
        }
        __syncthreads();

        float sc[8][4];
#pragma unroll
        for (int nt = 0; nt < 8; nt++)
#pragma unroll
            for (int r = 0; r < 4; r++) sc[nt][r] = 0.f;
#pragma unroll
        for (int ks = 0; ks < 8; ks++) {
#pragma unroll
            for (int nt = 0; nt < 8; nt++) {
                const int key = nt * 8 + g;
                uint32_t b0 = __float_as_uint(Ks[key * APAD + ks * 8 + tig]);
                uint32_t b1 = __float_as_uint(Ks[key * APAD + ks * 8 + tig + 4]);
                MMA_TF32(sc[nt], qa[ks], b0, b1);
            }
        }

        const bool diag = (kt == qb);
        const int row0 = wr + g, row1 = row0 + 8;
        float rm0 = -1e30f, rm1 = -1e30f;
#pragma unroll
        for (int nt = 0; nt < 8; nt++) {
            const int col0 = nt * 8 + tig * 2, col1 = col0 + 1;
            float s0 = sc[nt][0] * 0.125f; if (diag && col0 > row0) s0 = -1e30f;
            float s1 = sc[nt][1] * 0.125f; if (diag && col1 > row0) s1 = -1e30f;
            float s2 = sc[nt][2] * 0.125f; if (diag && col0 > row1) s2 = -1e30f;
            float s3 = sc[nt][3] * 0.125f; if (diag && col1 > row1) s3 = -1e30f;
            sc[nt][0] = s0; sc[nt][1] = s1; sc[nt][2] = s2; sc[nt][3] = s3;
            rm0 = fmaxf(rm0, fmaxf(s0, s1));
            rm1 = fmaxf(rm1, fmaxf(s2, s3));
        }
        rm0 = fmaxf(rm0, __shfl_xor_sync(0xFFFFFFFFu, rm0, 1));
        rm0 = fmaxf(rm0, __shfl_xor_sync(0xFFFFFFFFu, rm0, 2));
        rm1 = fmaxf(rm1, __shfl_xor_sync(0xFFFFFFFFu, rm1, 1));
        rm1 = fmaxf(rm1, __shfl_xor_sync(0xFFFFFFFFu, rm1, 2));

        const float mn0 = fmaxf(mrow0, rm0), mn1 = fmaxf(mrow1, rm1);
        const float corr0 = __expf(mrow0 - mn0), corr1 = __expf(mrow1 - mn1);
        mrow0 = mn0; mrow1 = mn1;

        float rs0 = 0.f, rs1 = 0.f;
#pragma unroll
        for (int nt = 0; nt < 8; nt++) {
            float p0 = __expf(sc[nt][0] - mn0);
            float p1 = __expf(sc[nt][1] - mn0);
            float p2 = __expf(sc[nt][2] - mn1);
            float p3 = __expf(sc[nt][3] - mn1);
            rs0 += p0 + p1; rs1 += p2 + p3;
            oc[nt][0] *= corr0; oc[nt][1] *= corr0;
            oc[nt][2] *= corr1; oc[nt][3] *= corr1;
            *reinterpret_cast<float2*>(&Ps[row0 * APAD + nt * 8 + tig * 2]) =
                make_float2(to_tf32(p0), to_tf32(p1));
            *reinterpret_cast<float2*>(&Ps[row1 * APAD + nt * 8 + tig * 2]) =
                make_float2(to_tf32(p2), to_tf32(p3));
        }
        rs0 += __shfl_xor_sync(0xFFFFFFFFu, rs0, 1);
        rs0 += __shfl_xor_sync(0xFFFFFFFFu, rs0, 2);
        rs1 += __shfl_xor_sync(0xFFFFFFFFu, rs1, 1);
        rs1 += __shfl_xor_sync(0xFFFFFFFFu, rs1, 2);
        lrow0 = lrow0 * corr0 + rs0;
        lrow1 = lrow1 * corr1 + rs1;
        __syncwarp();

#pragma unroll
        for (int ks = 0; ks < 8; ks++) {
            uint32_t pa[4];
            pa[0] = __float_as_uint(Ps[row0 * APAD + ks * 8 + tig]);
            pa[1] = __float_as_uint(Ps[row1 * APAD + ks * 8 + tig]);
            pa[2] = __float_as_uint(Ps[row0 * APAD + ks * 8 + tig + 4]);
            pa[3] = __float_as_uint(Ps[row1 * APAD + ks * 8 + tig + 4]);
#pragma unroll
            for (int nt = 0; nt < 8; nt++) {
                uint32_t b0 = __float_as_uint(Vs[(ks * 8 + tig) * APAD + nt * 8 + g]);
                uint32_t b1 = __float_as_uint(Vs[(ks * 8 + tig + 4) * APAD + nt * 8 + g]);
                MMA_TF32(oc[nt], pa, b0, b1);
            }
        }
        __syncwarp();
    }

    const float inv0 = 1.0f / lrow0, inv1 = 1.0f / lrow1;
    const size_t gr0 = (size_t)(b * SEQ + q0 + wr + g);
#pragma unroll
    for (int nt = 0; nt < 8; nt++) {
        const int col = h * HD + nt * 8 + tig * 2;
        *reinterpret_cast<float2*>(O + gr0 * DM + col) =
            make_float2(to_tf32(oc[nt][0] * inv0), to_tf32(oc[nt][1] * inv0));
        *reinterpret_cast<float2*>(O + (gr0 + 8) * DM + col) =
            make_float2(to_tf32(oc[nt][2] * inv1), to_tf32(oc[nt][3] * inv1));
    }
}

// ---------------- launch ----------------------------------------------------
extern "C" void kernel_launch(void* const* d_in, const int* in_sizes, int n_in,
                              void* d_out, int out_size) {
    const float* x  = (const float*)d_in[0];
    const float* Wq = (const float*)d_in[1];
    const float* Wk = (const float*)d_in[2];
    const float* Wv = (const float*)d_in[3];
    const float* Wo = (const float*)d_in[4];
    float* out = (float*)d_out;

    float *gq, *gk, *gv, *go, *xt, *wq, *wk, *wv, *wo;
    cudaGetSymbolAddress((void**)&gq, g_q);
    cudaGetSymbolAddress((void**)&gk, g_k);
    cudaGetSymbolAddress((void**)&gv, g_v);
    cudaGetSymbolAddress((void**)&go, g_o);
    cudaGetSymbolAddress((void**)&xt, g_xt);
    cudaGetSymbolAddress((void**)&wq, g_wq);
    cudaGetSymbolAddress((void**)&wk, g_wk);
    cudaGetSymbolAddress((void**)&wv, g_wv);
    cudaGetSymbolAddress((void**)&wo, g_wo);

    static bool attr_set = false;
    if (!attr_set) {
        cudaFuncSetAttribute(gemm_qkv, cudaFuncAttributeMaxDynamicSharedMemorySize, GEMM_SMEM);
        cudaFuncSetAttribute(gemm_single, cudaFuncAttributeMaxDynamicSharedMemorySize, GEMM_SMEM);
        cudaFuncSetAttribute(attn_mma, cudaFuncAttributeMaxDynamicSharedMemorySize, ATTN_SMEM);
        attr_set = true;
    }

    // pre-round all operands to tf32 values (one launch)
    cvt_all_kernel<<<1184, 256>>>(
        (const float4*)x,  (float4*)xt, (int)((size_t)NT * DM / 4),
        (const float4*)Wq, (float4*)wq, (int)((size_t)DM * DM / 4),
        (const float4*)Wk, (float4*)wk, (int)((size_t)(NKV * HD) * DM / 4),
        (const float4*)Wv, (float4*)wv, (int)((size_t)(NKV * HD) * DM / 4),
        (const float4*)Wo, (float4*)wo, (int)((size_t)DM * DM / 4));

    // Q + K + V projections, one launch (768 CTAs)
    gemm_qkv<<<768, 256, GEMM_SMEM>>>(xt, wq, gq, wk, gk, wv, gv);

    // RoPE on q and k, one launch
    int tq = NT * NH * 32;
    int tk = NT * NKV * 32;
    rope_all<<<(tq + tk + 255) / 256, 256>>>(gq, gk, tq, tq + tk);

    // causal GQA attention (tf32 mma flash, longest-first)
    attn_mma<<<dim3(SEQ / 64, B_SZ * NH), 128, ATTN_SMEM>>>(gq, gk, gv, go);

    // output projection into d_out
    gemm_single<<<dim3(DM / 128, NT / 128), 256, GEMM_SMEM>>>(go, wo, out, DM, DM);
}

// round 12
// speedup vs baseline: 1.4311x; 1.0597x over previous
#include <cuda_runtime.h>
#include <cstdint>

#define B_SZ   2
#define SEQ    2048
#define DM     2048
#define NH     32
#define NKV    8
#define HD     64
#define NT     (B_SZ * SEQ)   // 4096 tokens

// ---------------- scratch (static device globals; no runtime allocation) ----
__device__ float g_q[(size_t)NT * DM];          // 32 MB
__device__ float g_k[(size_t)NT * NKV * HD];    //  8 MB
__device__ float g_v[(size_t)NT * NKV * HD];    //  8 MB
__device__ float g_o[(size_t)NT * DM];          // 32 MB (attention writes tf32-rounded)
__device__ float g_xt[(size_t)NT * DM];         // 32 MB
__device__ float g_wq[(size_t)DM * DM];         // 16 MB
__device__ float g_wk[(size_t)(NKV * HD) * DM]; //  4 MB
__device__ float g_wv[(size_t)(NKV * HD) * DM]; //  4 MB
__device__ float g_wo[(size_t)DM * DM];         // 16 MB

__device__ __forceinline__ float to_tf32(float x) {
    asm("cvt.rna.tf32.f32 %0, %1;" : "=f"(x) : "f"(x));
    return x;
}

#define MMA_TF32(c, a, b0_, b1_) \
    asm volatile("mma.sync.aligned.m16n8k8.row.col.f32.tf32.tf32.f32 " \
                 "{%0,%1,%2,%3}, {%4,%5,%6,%7}, {%8,%9}, {%0,%1,%2,%3};" \
                 : "+f"((c)[0]), "+f"((c)[1]), "+f"((c)[2]), "+f"((c)[3]) \
                 : "r"((a)[0]), "r"((a)[1]), "r"((a)[2]), "r"((a)[3]), \
                   "r"(b0_), "r"(b1_))

__device__ __forceinline__ void cp16(uint32_t dst, const void* src) {
    asm volatile("cp.async.ca.shared.global [%0], [%1], 16;" :: "r"(dst), "l"(src));
}
__device__ __forceinline__ uint32_t smem_u32(const void* p) {
    uint32_t a;
    asm("{ .reg .u64 t; cvta.to.shared.u64 t, %1; cvt.u32.u64 %0, t; }" : "=r"(a) : "l"(p));
    return a;
}

// ---------------- tf32 pre-rounding pass (all 5 tensors, one launch) --------
__global__ void cvt_all_kernel(const float4* __restrict__ s0, float4* __restrict__ d0, int n0,
                               const float4* __restrict__ s1, float4* __restrict__ d1, int n1,
                               const float4* __restrict__ s2, float4* __restrict__ d2, int n2,
                               const float4* __restrict__ s3, float4* __restrict__ d3, int n3,
                               const float4* __restrict__ s4, float4* __restrict__ d4, int n4) {
    const int stride = gridDim.x * blockDim.x;
    const int gid = blockIdx.x * blockDim.x + threadIdx.x;
#define CVT_SEG(S, D, N) \
    for (int i = gid; i < (N); i += stride) { \
        float4 v = (S)[i]; \
        v.x = to_tf32(v.x); v.y = to_tf32(v.y); \
        v.z = to_tf32(v.z); v.w = to_tf32(v.w); \
        (D)[i] = v; \
    }
    CVT_SEG(s0, d0, n0)
    CVT_SEG(s1, d1, n1)
    CVT_SEG(s2, d2, n2)
    CVT_SEG(s3, d3, n3)
    CVT_SEG(s4, d4, n4)
#undef CVT_SEG
}

// ============ tf32 tensor GEMM core (pre-rounded operands) ==================
#define BK 32
#define LDS_PAD 36
#define STAGE_F (128 * LDS_PAD)
#define STAGES 3
#define GEMM_SMEM (STAGES * 2 * STAGE_F * 4)     // 110592 B

__device__ __forceinline__ void gemm_tile(const float* __restrict__ A,
                                          const float* __restrict__ Bm,
                                          float* __restrict__ C,
                                          int N, int K, int m0, int n0,
                                          float* smem) {
    const uint32_t sb = smem_u32(smem);
    const int tid = threadIdx.x;
    const int wid = tid >> 5;
    const int lane = tid & 31;
    const int g   = lane >> 2;
    const int tig = lane & 3;
    const int wm0 = (wid & 3) * 32;
    const int wn0 = (wid >> 2) * 64;

    float acc[2][8][4];
#pragma unroll
    for (int mt = 0; mt < 2; mt++)
#pragma unroll
        for (int nt = 0; nt < 8; nt++)
#pragma unroll
            for (int r = 0; r < 4; r++) acc[mt][nt][r] = 0.f;

    const int NITER = K / BK;

    auto issue_stage = [&](int kt, int s) {
        const int k0 = kt * BK;
        const uint32_t abase = sb + (uint32_t)(s * 2 * STAGE_F) * 4u;
        const uint32_t bbase = abase + (uint32_t)STAGE_F * 4u;
#pragma unroll
        for (int t = 0; t < 4; t++) {
            const int e = tid + t * 256;
            const int r = e >> 3;
            const int c = (e & 7) * 4;
            const uint32_t soff = (uint32_t)(r * LDS_PAD + c) * 4u;
            cp16(abase + soff, A  + (size_t)(m0 + r) * K + k0 + c);
            cp16(bbase + soff, Bm + (size_t)(n0 + r) * K + k0 + c);
        }
    };

#pragma unroll
    for (int s = 0; s < STAGES - 1; s++) {
        if (s < NITER) issue_stage(s, s);
        asm volatile("cp.async.commit_group;");
    }

    for (int i = 0; i < NITER; i++) {
        asm volatile("cp.async.wait_group %0;" :: "n"(STAGES - 2));
        __syncthreads();

        const float* As = smem + (i % STAGES) * 2 * STAGE_F;
        const float* Bs = As + STAGE_F;
#pragma unroll
        for (int ks = 0; ks < 4; ks++) {
            const int k = ks * 8;
            uint32_t af[2][4], bf[8][2];
#pragma unroll
            for (int mt = 0; mt < 2; mt++) {
                const int am = wm0 + mt * 16 + g;
                af[mt][0] = __float_as_uint(As[(am)     * LDS_PAD + k + tig]);
                af[mt][1] = __float_as_uint(As[(am + 8) * LDS_PAD + k + tig]);
                af[mt][2] = __float_as_uint(As[(am)     * LDS_PAD + k + tig + 4]);
                af[mt][3] = __float_as_uint(As[(am + 8) * LDS_PAD + k + tig + 4]);
            }
#pragma unroll
            for (int nt = 0; nt < 8; nt++) {
                const int bn = wn0 + nt * 8 + g;
                bf[nt][0] = __float_as_uint(Bs[bn * LDS_PAD + k + tig]);
                bf[nt][1] = __float_as_uint(Bs[bn * LDS_PAD + k + tig + 4]);
            }
#pragma unroll
            for (int mt = 0; mt < 2; mt++)
#pragma unroll
                for (int nt = 0; nt < 8; nt++)
                    MMA_TF32(acc[mt][nt], af[mt], bf[nt][0], bf[nt][1]);
        }

        if (i + STAGES - 1 < NITER) issue_stage(i + STAGES - 1, (i + STAGES - 1) % STAGES);
        asm volatile("cp.async.commit_group;");
    }

#pragma unroll
    for (int mt = 0; mt < 2; mt++) {
        const int row = m0 + wm0 + mt * 16 + g;
#pragma unroll
        for (int nt = 0; nt < 8; nt++) {
            const int col = n0 + wn0 + nt * 8 + tig * 2;
            const float* c = acc[mt][nt];
            *reinterpret_cast<float2*>(C + (size_t)row * N + col) = make_float2(c[0], c[1]);
            *reinterpret_cast<float2*>(C + (size_t)(row + 8) * N + col) = make_float2(c[2], c[3]);
        }
    }
}

// Q + K + V projections in one launch. bid 0..511 -> Q, 512..639 -> K, 640..767 -> V.
__global__ void __launch_bounds__(256, 2)
gemm_qkv(const float* __restrict__ A,
         const float* __restrict__ Bq, float* __restrict__ Cq,
         const float* __restrict__ Bk, float* __restrict__ Ck,
         const float* __restrict__ Bv, float* __restrict__ Cv) {
    extern __shared__ float smem[];
    const int bid = blockIdx.x;
    if (bid < 512) {
        gemm_tile(A, Bq, Cq, DM, DM, (bid >> 4) * 128, (bid & 15) * 128, smem);
    } else if (bid < 640) {
        const int t = bid - 512;
        gemm_tile(A, Bk, Ck, NKV * HD, DM, (t >> 2) * 128, (t & 3) * 128, smem);
    } else {
        const int t = bid - 640;
        gemm_tile(A, Bv, Cv, NKV * HD, DM, (t >> 2) * 128, (t & 3) * 128, smem);
    }
}

// O projection (single matrix)
__global__ void __launch_bounds__(256, 2)
gemm_single(const float* __restrict__ A, const float* __restrict__ Bm,
            float* __restrict__ C, int N, int K) {
    extern __shared__ float smem[];
    gemm_tile(A, Bm, C, N, K, blockIdx.y * 128, blockIdx.x * 128, smem);
}

// ---------------- RoPE (q and k in one launch) ------------------------------
__global__ void rope_all(float* __restrict__ q, float* __restrict__ k,
                         int tq, int total) {
    int idx = blockIdx.x * blockDim.x + threadIdx.x;
    if (idx >= total) return;
    float* buf;
    int nheads;
    if (idx < tq) { buf = q; nheads = NH; }
    else          { idx -= tq; buf = k; nheads = NKV; }
    int d   = idx & 31;
    int h   = (idx >> 5) % nheads;
    int row = idx / (32 * nheads);
    int s   = row & (SEQ - 1);
    float inv = expf(-(float)d * (9.210340371976184f / 32.0f));
    float ang = (float)s * inv;
    float c  = cosf(ang);
    float si = sinf(ang);
    float* p = buf + (size_t)row * (nheads * HD) + h * HD;
    float x1 = p[d];
    float x2 = p[d + 32];
    p[d]      = x1 * c - x2 * si;
    p[d + 32] = x2 * c + x1 * si;
}

// ======== causal GQA flash attention: 128 q-rows/block, 32 q-rows/warp ======
// 4 warps. Each K/V b-frag feeds two MMAs (mt=0,1) -> ~half the LDS per MMA.
// Key tiles of 64; mask via global row/col compare on the last two tiles.
#define APAD 68
#define ATTN_SMEM ((64 + 64 + 128) * APAD * 4)   // Ks, Vs, Ps(128 rows) = 69632 B

__global__ void __launch_bounds__(128)
attn_mma(const float* __restrict__ Q, const float* __restrict__ K,
         const float* __restrict__ V, float* __restrict__ O) {
    extern __shared__ float sm[];
    float* Ks = sm;
    float* Vs = sm + 64 * APAD;
    float* Ps = sm + 2 * 64 * APAD;   // 128 rows

    // longest-first: high-qb blocks launch first
    const int qb = (int)gridDim.x - 1 - (int)blockIdx.x;   // 0..15
    const int bh = blockIdx.y;
    const int b   = bh >> 5;
    const int h   = bh & 31;
    const int kvh = h >> 2;
    const int tid = threadIdx.x;
    const int wid = tid >> 5;
    const int lane = tid & 31;
    const int g   = lane >> 2;
    const int tig = lane & 3;
    const int q0 = qb * 128;
    const int wr = wid * 32;          // warp's first q-row (local)

    // ---- stage Q tile (128 rows x 16 float4) into Ps, pull a-frags ----
#pragma unroll
    for (int t = 0; t < 16; t++) {
        int e = tid + t * 128;        // 0..2047
        int r = e >> 4;               // 0..127
        int c = (e & 15) * 4;
        float4 v = *reinterpret_cast<const float4*>(
            Q + (size_t)(b * SEQ + q0 + r) * DM + h * HD + c);
        *reinterpret_cast<float4*>(&Ps[r * APAD + c]) = v;
    }
    __syncthreads();
    uint32_t qa[2][8][4];
#pragma unroll
    for (int mt = 0; mt < 2; mt++) {
        const int r0 = wr + mt * 16 + g, r1 = r0 + 8;
#pragma unroll
        for (int ks = 0; ks < 8; ks++) {
            const int c0 = ks * 8 + tig, c1 = c0 + 4;
            qa[mt][ks][0] = __float_as_uint(to_tf32(Ps[r0 * APAD + c0]));
            qa[mt][ks][1] = __float_as_uint(to_tf32(Ps[r1 * APAD + c0]));
            qa[mt][ks][2] = __float_as_uint(to_tf32(Ps[r0 * APAD + c1]));
            qa[mt][ks][3] = __float_as_uint(to_tf32(Ps[r1 * APAD + c1]));
        }
    }
    __syncthreads();

    float oc[2][8][4];
#pragma unroll
    for (int mt = 0; mt < 2; mt++)
#pragma unroll
        for (int nt = 0; nt < 8; nt++)
#pragma unroll
            for (int r = 0; r < 4; r++) oc[mt][nt][r] = 0.f;
    float mrow[2][2] = {{-1e30f, -1e30f}, {-1e30f, -1e30f}};
    float lrow[2][2] = {{0.f, 0.f}, {0.f, 0.f}};

    const int nkt = 2 * qb + 2;
    for (int kt = 0; kt < nkt; kt++) {
        __syncthreads();   // prior PV reads of Vs done before overwrite
        // ---- load K and V tiles (rna-rounded): 64 rows x 16 float4 ----
#pragma unroll
        for (int t = 0; t < 8; t++) {
            int e = tid + t * 128;
            int r = e >> 4;
            int c = (e & 15) * 4;
            size_t go = (size_t)(b * SEQ + kt * 64 + r) * (NKV * HD) + kvh * HD + c;
            float4 kv = *reinterpret_cast<const float4*>(K + go);
            kv.x = to_tf32(kv.x); kv.y = to_tf32(kv.y);
            kv.z = to_tf32(kv.z); kv.w = to_tf32(kv.w);
            *reinterpret_cast<float4*>(&Ks[r * APAD + c]) = kv;
            float4 vv = *reinterpret_cast<const float4*>(V + go);
            vv.x = to_tf32(vv.x); vv.y = to_tf32(vv.y);
            vv.z = to_tf32(vv.z); vv.w = to_tf32(vv.w);
            *reinterpret_cast<float4*>(&Vs[r * APAD + c]) = vv;
        }
        __syncthreads();

        // ---- S = Q K^T: each K b-frag feeds both m-frags ----
        float sc[2][8][4];
#pragma unroll
        for (int mt = 0; mt < 2; mt++)
#pragma unroll
            for (int nt = 0; nt < 8; nt++)
#pragma unroll
                for (int r = 0; r < 4; r++) sc[mt][nt][r] = 0.f;
#pragma unroll
        for (int ks = 0; ks < 8; ks++) {
#pragma unroll
            for (int nt = 0; nt < 8; nt++) {
                const int key = nt * 8 + g;
                uint32_t b0 = __float_as_uint(Ks[key * APAD + ks * 8 + tig]);
                uint32_t b1 = __float_as_uint(Ks[key * APAD + ks * 8 + tig + 4]);
                MMA_TF32(sc[0][nt], qa[0][ks], b0, b1);
                MMA_TF32(sc[1][nt], qa[1][ks], b0, b1);
            }
        }

        // ---- scale + causal mask (global compare on tail tiles) + softmax ----
        const bool tail = (kt >= 2 * qb);
#pragma unroll
        for (int mt = 0; mt < 2; mt++) {
            const int row0 = wr + mt * 16 + g, row1 = row0 + 8;
            const int gr0 = q0 + row0, gr1 = q0 + row1;
            float rm0 = -1e30f, rm1 = -1e30f;
#pragma unroll
            for (int nt = 0; nt < 8; nt++) {
                const int gc0 = kt * 64 + nt * 8 + tig * 2, gc1 = gc0 + 1;
                float s0 = sc[mt][nt][0] * 0.125f; if (tail && gc0 > gr0) s0 = -1e30f;
                float s1 = sc[mt][nt][1] * 0.125f; if (tail && gc1 > gr0) s1 = -1e30f;
                float s2 = sc[mt][nt][2] * 0.125f; if (tail && gc0 > gr1) s2 = -1e30f;
                float s3 = sc[mt][nt][3] * 0.125f; if (tail && gc1 > gr1) s3 = -1e30f;
                sc[mt][nt][0] = s0; sc[mt][nt][1] = s1;
                sc[mt][nt][2] = s2; sc[mt][nt][3] = s3;
                rm0 = fmaxf(rm0, fmaxf(s0, s1));
                rm1 = fmaxf(rm1, fmaxf(s2, s3));
            }
            rm0 = fmaxf(rm0, __shfl_xor_sync(0xFFFFFFFFu, rm0, 1));
            rm0 = fmaxf(rm0, __shfl_xor_sync(0xFFFFFFFFu, rm0, 2));
            rm1 = fmaxf(rm1, __shfl_xor_sync(0xFFFFFFFFu, rm1, 1));
            rm1 = fmaxf(rm1, __shfl_xor_sync(0xFFFFFFFFu, rm1, 2));

            const float mn0 = fmaxf(mrow[mt][0], rm0), mn1 = fmaxf(mrow[mt][1], rm1);
            const float corr0 = __expf(mrow[mt][0] - mn0), corr1 = __expf(mrow[mt][1] - mn1);
            mrow[mt][0] = mn0; mrow[mt][1] = mn1;

            float rs0 = 0.f, rs1 = 0.f;
#pragma unroll
            for (int nt = 0; nt < 8; nt++) {
                float p0 = __expf(sc[mt][nt][0] - mn0);
                float p1 = __expf(sc[mt][nt][1] - mn0);
                float p2 = __expf(sc[mt][nt][2] - mn1);
                float p3 = __expf(sc[mt][nt][3] - mn1);
                rs0 += p0 + p1; rs1 += p2 + p3;
                oc[mt][nt][0] *= corr0; oc[mt][nt][1] *= corr0;
                oc[mt][nt][2] *= corr1; oc[mt][nt][3] *= corr1;
                *reinterpret_cast<float2*>(&Ps[row0 * APAD + nt * 8 + tig * 2]) =
                    make_float2(to_tf32(p0), to_tf32(p1));
                *reinterpret_cast<float2*>(&Ps[row1 * APAD + nt * 8 + tig * 2]) =
                    make_float2(to_tf32(p2), to_tf32(p3));
            }
            rs0 += __shfl_xor_sync(0xFFFFFFFFu, rs0, 1);
            rs0 += __shfl_xor_sync(0xFFFFFFFFu, rs0, 2);
            rs1 += __shfl_xor_sync(0xFFFFFFFFu, rs1, 1);
            rs1 += __shfl_xor_sync(0xFFFFFFFFu, rs1, 2);
            lrow[mt][0] = lrow[mt][0] * corr0 + rs0;
            lrow[mt][1] = lrow[mt][1] * corr1 + rs1;
        }
        __syncwarp();

        // ---- O += P V: each V b-frag feeds both m-frags ----
#pragma unroll
        for (int ks = 0; ks < 8; ks++) {
            uint32_t pa[2][4];
#pragma unroll
            for (int mt = 0; mt < 2; mt++) {
                const int row0 = wr + mt * 16 + g, row1 = row0 + 8;
                pa[mt][0] = __float_as_uint(Ps[row0 * APAD + ks * 8 + tig]);
                pa[mt][1] = __float_as_uint(Ps[row1 * APAD + ks * 8 + tig]);
                pa[mt][2] = __float_as_uint(Ps[row0 * APAD + ks * 8 + tig + 4]);
                pa[mt][3] = __float_as_uint(Ps[row1 * APAD + ks * 8 + tig + 4]);
            }
#pragma unroll
            for (int nt = 0; nt < 8; nt++) {
                uint32_t b0 = __float_as_uint(Vs[(ks * 8 + tig) * APAD + nt * 8 + g]);
                uint32_t b1 = __float_as_uint(Vs[(ks * 8 + tig + 4) * APAD + nt * 8 + g]);
                MMA_TF32(oc[0][nt], pa[0], b0, b1);
                MMA_TF32(oc[1][nt], pa[1], b0, b1);
            }
        }
        __syncwarp();   // Ps reads done before next tile's stores
    }

    // ---- finalize (tf32-rounded store pre-rounds the O-proj A operand) ----
#pragma unroll
    for (int mt = 0; mt < 2; mt++) {
        const float inv0 = 1.0f / lrow[mt][0], inv1 = 1.0f / lrow[mt][1];
        const size_t gr0 = (size_t)(b * SEQ + q0 + wr + mt * 16 + g);
#pragma unroll
        for (int nt = 0; nt < 8; nt++) {
            const int col = h * HD + nt * 8 + tig * 2;
            *reinterpret_cast<float2*>(O + gr0 * DM + col) =
                make_float2(to_tf32(oc[mt][nt][0] * inv0), to_tf32(oc[mt][nt][1] * inv0));
            *reinterpret_cast<float2*>(O + (gr0 + 8) * DM + col) =
                make_float2(to_tf32(oc[mt][nt][2] * inv1), to_tf32(oc[mt][nt][3] * inv1));
        }
    }
}

// ---------------- launch ----------------------------------------------------
extern "C" void kernel_launch(void* const* d_in, const int* in_sizes, int n_in,
                              void* d_out, int out_size) {
    const float* x  = (const float*)d_in[0];
    const float* Wq = (const float*)d_in[1];
    const float* Wk = (const float*)d_in[2];
    const float* Wv = (const float*)d_in[3];
    const float* Wo = (const float*)d_in[4];
    float* out = (float*)d_out;

    float *gq, *gk, *gv, *go, *xt, *wq, *wk, *wv, *wo;
    cudaGetSymbolAddress((void**)&gq, g_q);
    cudaGetSymbolAddress((void**)&gk, g_k);
    cudaGetSymbolAddress((void**)&gv, g_v);
    cudaGetSymbolAddress((void**)&go, g_o);
    cudaGetSymbolAddress((void**)&xt, g_xt);
    cudaGetSymbolAddress((void**)&wq, g_wq);
    cudaGetSymbolAddress((void**)&wk, g_wk);
    cudaGetSymbolAddress((void**)&wv, g_wv);
    cudaGetSymbolAddress((void**)&wo, g_wo);

    static bool attr_set = false;
    if (!attr_set) {
        cudaFuncSetAttribute(gemm_qkv, cudaFuncAttributeMaxDynamicSharedMemorySize, GEMM_SMEM);
        cudaFuncSetAttribute(gemm_single, cudaFuncAttributeMaxDynamicSharedMemorySize, GEMM_SMEM);
        cudaFuncSetAttribute(attn_mma, cudaFuncAttributeMaxDynamicSharedMemorySize, ATTN_SMEM);
        attr_set = true;
    }

    // pre-round all operands to tf32 values (one launch)
    cvt_all_kernel<<<1184, 256>>>(
        (const float4*)x,  (float4*)xt, (int)((size_t)NT * DM / 4),
        (const float4*)Wq, (float4*)wq, (int)((size_t)DM * DM / 4),
        (const float4*)Wk, (float4*)wk, (int)((size_t)(NKV * HD) * DM / 4),
        (const float4*)Wv, (float4*)wv, (int)((size_t)(NKV * HD) * DM / 4),
        (const float4*)Wo, (float4*)wo, (int)((size_t)DM * DM / 4));

    // Q + K + V projections, one launch (768 CTAs)
    gemm_qkv<<<768, 256, GEMM_SMEM>>>(xt, wq, gq, wk, gk, wv, gv);

    // RoPE on q and k, one launch
    int tq = NT * NH * 32;
    int tk = NT * NKV * 32;
    rope_all<<<(tq + tk + 255) / 256, 256>>>(gq, gk, tq, tq + tk);

    // causal GQA attention (tf32 mma flash, 128 q-rows/block, longest-first)
    attn_mma<<<dim3(SEQ / 128, B_SZ * NH), 128, ATTN_SMEM>>>(gq, gk, gv, go);

    // output projection into d_out
    gemm_single<<<dim3(DM / 128, NT / 128), 256, GEMM_SMEM>>>(go, wo, out, DM, DM);
}